// round 1
// baseline (speedup 1.0000x reference)
#include <cuda_runtime.h>
#include <math.h>
#include <stdint.h>

// ---------------- problem constants ----------------
#define N_ATOMS   20000
#define N_EDGES   640000
#define N_STRUCT  100
#define N_SPECIES 4
#define N_RADIAL  8
#define N_SPH     16
#define Q_DIM     32                // N_SPECIES * N_RADIAL
#define C_PER_ATOM 512              // Q_DIM * N_SPH
#define PS_DIM    4096              // (L_MAX+1) * Q * Q
#define HID       256
#define CUTOFF    5.0f
#define EPSR      1e-12f

// ---------------- scratch (static device globals; no allocation) ----------------
__device__ float g_c [(size_t)N_ATOMS * C_PER_ATOM];        // 41 MB
__device__ float g_ps[(size_t)N_ATOMS * PS_DIM];            // 328 MB
__device__ float g_h1[(size_t)N_ATOMS * HID];               // 20.5 MB
__device__ float g_h2[(size_t)N_ATOMS * HID];               // 20.5 MB
__device__ int   g_counts[N_SPECIES];
__device__ int   g_off[N_SPECIES];
__device__ int   g_cursor[N_SPECIES];
__device__ int   g_sorted[N_ATOMS];

// ---------------- helpers ----------------
__device__ __forceinline__ void red4(float* p, float a, float b, float c, float d) {
    asm volatile("red.global.add.v4.f32 [%0], {%1,%2,%3,%4};"
                 :: "l"(p), "f"(a), "f"(b), "f"(c), "f"(d) : "memory");
}

__device__ __forceinline__ float silu(float x) {
    return x / (1.0f + expf(-x));
}

// ---------------- K0: zero scratch + output + counters ----------------
__global__ void zero_kernel(float* __restrict__ out) {
    size_t idx = (size_t)blockIdx.x * blockDim.x + threadIdx.x;
    // zero g_c as float4: N_ATOMS*512/4 = 2,560,000 float4s; grid sized exactly
    float4* c4 = reinterpret_cast<float4*>(g_c);
    c4[idx] = make_float4(0.f, 0.f, 0.f, 0.f);
    if (idx < N_STRUCT) out[idx] = 0.f;
    if (idx < N_SPECIES) g_counts[idx] = 0;
}

// ---------------- K1: composition energy + species histogram ----------------
__global__ void atom_prep_kernel(const int* __restrict__ numbers,
                                 const int* __restrict__ batch,
                                 const float* __restrict__ Wc,
                                 float* __restrict__ out) {
    int a = blockIdx.x * blockDim.x + threadIdx.x;
    if (a >= N_ATOMS) return;
    int s = numbers[a];
    atomicAdd(&g_counts[s], 1);
    atomicAdd(&out[batch[a]], Wc[s]);
}

// ---------------- K2: exclusive scan over 4 species counts ----------------
__global__ void offsets_kernel() {
    if (threadIdx.x == 0) {
        int acc = 0;
        for (int s = 0; s < N_SPECIES; s++) {
            g_off[s] = acc;
            g_cursor[s] = acc;
            acc += g_counts[s];
        }
    }
}

// ---------------- K3: scatter atoms into species-sorted order ----------------
__global__ void scatter_kernel(const int* __restrict__ numbers) {
    int a = blockIdx.x * blockDim.x + threadIdx.x;
    if (a >= N_ATOMS) return;
    int s = numbers[a];
    int pos = atomicAdd(&g_cursor[s], 1);
    g_sorted[pos] = a;
}

// ---------------- K4: edge featurization + segment reduction into g_c ----------------
__global__ void edge_kernel(const float* __restrict__ pos,
                            const float* __restrict__ cells,
                            const int* __restrict__ numbers,
                            const int* __restrict__ ei,
                            const int* __restrict__ eoff,
                            const int* __restrict__ batch) {
    int e = blockIdx.x * blockDim.x + threadIdx.x;
    if (e >= N_EDGES) return;
    int i = ei[e];
    int j = ei[N_EDGES + e];

    float pix = pos[3*i+0], piy = pos[3*i+1], piz = pos[3*i+2];
    float pjx = pos[3*j+0], pjy = pos[3*j+1], pjz = pos[3*j+2];

    int o0 = eoff[3*e+0], o1 = eoff[3*e+1], o2 = eoff[3*e+2];
    float sx = 0.f, sy = 0.f, sz = 0.f;
    if (o0 | o1 | o2) {
        int b = batch[i];
        const float* cb = cells + (size_t)b * 9;
        float f0 = (float)o0, f1 = (float)o1, f2 = (float)o2;
        sx = f0*cb[0] + f1*cb[3] + f2*cb[6];
        sy = f0*cb[1] + f1*cb[4] + f2*cb[7];
        sz = f0*cb[2] + f1*cb[5] + f2*cb[8];
    }

    float dx = pjx - pix + sx;
    float dy = pjy - piy + sy;
    float dz = pjz - piz + sz;
    float r2 = dx*dx + dy*dy + dz*dz + EPSR;
    float r  = sqrtf(r2);
    if (r >= CUTOFF) return;          // fc == 0 -> zero contribution

    float inv = 1.0f / r;
    float a_c = r * (1.0f / CUTOFF);  // r/cutoff in [0,1)
    float fc  = 0.5f * (cospif(a_c) + 1.0f);
    float x = dx * inv, y = dy * inv, z = dz * inv;
    float x2 = x*x, y2 = y*y, z2 = z*z;

    float Y[16];
    Y[0]  = 0.28209479177387814f;
    Y[1]  = 0.4886025119029199f * y;
    Y[2]  = 0.4886025119029199f * z;
    Y[3]  = 0.4886025119029199f * x;
    Y[4]  = 1.0925484305920792f * x * y;
    Y[5]  = 1.0925484305920792f * y * z;
    Y[6]  = 0.31539156525252005f * (3.0f*z2 - 1.0f);
    Y[7]  = 1.0925484305920792f * x * z;
    Y[8]  = 0.5462742152960396f * (x2 - y2);
    Y[9]  = 0.5900435899266435f * y * (3.0f*x2 - y2);
    Y[10] = 2.890611442640554f  * x * y * z;
    Y[11] = 0.4570457994644658f * y * (5.0f*z2 - 1.0f);
    Y[12] = 0.3731763325901154f * z * (5.0f*z2 - 3.0f);
    Y[13] = 0.4570457994644658f * x * (5.0f*z2 - 1.0f);
    Y[14] = 1.445305721320277f  * z * (x2 - y2);
    Y[15] = 0.5900435899266435f * x * (x2 - 3.0f*y2);

    float rn[N_RADIAL];
    float scale = inv * fc;
    #pragma unroll
    for (int n = 0; n < N_RADIAL; n++)
        rn[n] = sinpif((float)(n + 1) * a_c) * scale;

    int sj = numbers[j];
    float* base = g_c + ((size_t)i * N_SPECIES + sj) * (N_RADIAL * N_SPH);

    #pragma unroll
    for (int n = 0; n < N_RADIAL; n++) {
        float rv = rn[n];
        #pragma unroll
        for (int m4 = 0; m4 < 4; m4++) {
            red4(base + n*16 + m4*4,
                 rv * Y[m4*4 + 0], rv * Y[m4*4 + 1],
                 rv * Y[m4*4 + 2], rv * Y[m4*4 + 3]);
        }
    }
}

// ---------------- K5: power spectrum per atom ----------------
__global__ void ps_kernel() {
    __shared__ float cs[C_PER_ATOM];
    int a = blockIdx.x;
    int t = threadIdx.x;      // 128 threads
    const float4* ca = reinterpret_cast<const float4*>(g_c + (size_t)a * C_PER_ATOM);
    reinterpret_cast<float4*>(cs)[t] = ca[t];
    __syncthreads();

    const float norm[4] = {1.0f, 0.5773502691896258f, 0.4472135954999579f, 0.3779644730092272f};
    float* outp = g_ps + (size_t)a * PS_DIM;

    #pragma unroll
    for (int w = 0; w < 32; w++) {
        int idx = w * 128 + t;        // 0..4095
        int l   = idx >> 10;
        int rem = idx & 1023;
        int q   = rem >> 5;
        int p   = rem & 31;
        int m0 = l * l;
        int m1 = (l + 1) * (l + 1);
        float sum = 0.f;
        for (int m = m0; m < m1; m++)
            sum += cs[q * 16 + m] * cs[p * 16 + m];
        outp[idx] = sum * norm[l];
    }
}

// ---------------- K6/K7: species-grouped SGEMM  (M-tile 64, N=256, K-tile 8) ----------------
// WHICH==1: A=g_ps (gathered rows), C=g_h1, K=4096.  WHICH==2: A=g_h1, C=g_h2, K=256.
template<int WHICH>
__global__ void __launch_bounds__(256) gemm_kernel(const float* __restrict__ Wbase, int K) {
    const int s    = blockIdx.y;
    const int mloc = blockIdx.x * 64;
    const int count = g_counts[s];
    if (mloc >= count) return;
    const int row0   = g_off[s] + mloc;
    const int mcount = min(64, count - mloc);
    const float* W = Wbase + (size_t)s * K * HID;

    const float* A = (WHICH == 1) ? g_ps : g_h1;
    float*       C = (WHICH == 1) ? g_h1 : g_h2;

    __shared__ float As[2][8][64];
    __shared__ float Bs[2][8][256];

    const int t  = threadIdx.x;
    const int tm = t >> 5;          // 0..7   -> rows tm*8..tm*8+7
    const int tn = t & 31;          // 0..31  -> cols tn*8..tn*8+7

    // A staging: thread loads float2 at (row am, k-offset ak)
    const int am = t >> 2;          // 0..63
    const int ak = (t & 3) * 2;     // 0,2,4,6
    const bool avalid = (am < mcount);
    const float* Arow = A;          // dummy init
    if (avalid) {
        int r = row0 + am;
        int src = (WHICH == 1) ? g_sorted[r] : r;
        Arow = A + (size_t)src * K;
    }
    // B staging: thread loads 8 floats at (k-row bk, col bn)
    const int bk = t >> 5;          // 0..7
    const int bn = (t & 31) * 8;    // 0..248

    float acc[8][8];
    #pragma unroll
    for (int i = 0; i < 8; i++)
        #pragma unroll
        for (int j = 0; j < 8; j++) acc[i][j] = 0.f;

    const int NT = K >> 3;

    // prologue: tile 0 -> smem buf 0
    {
        float2 ar = avalid ? *reinterpret_cast<const float2*>(Arow + ak)
                           : make_float2(0.f, 0.f);
        float4 b0 = *reinterpret_cast<const float4*>(W + (size_t)bk * HID + bn);
        float4 b1 = *reinterpret_cast<const float4*>(W + (size_t)bk * HID + bn + 4);
        As[0][ak][am] = ar.x; As[0][ak + 1][am] = ar.y;
        *reinterpret_cast<float4*>(&Bs[0][bk][bn])     = b0;
        *reinterpret_cast<float4*>(&Bs[0][bk][bn + 4]) = b1;
    }
    __syncthreads();

    for (int kt = 0; kt < NT; kt++) {
        const int cur = kt & 1, nxt = cur ^ 1;
        const bool has_next = (kt + 1 < NT);

        float2 a_n = make_float2(0.f, 0.f);
        float4 b0n, b1n;
        if (has_next) {
            int kbase = (kt + 1) * 8;
            if (avalid) a_n = *reinterpret_cast<const float2*>(Arow + kbase + ak);
            b0n = *reinterpret_cast<const float4*>(W + (size_t)(kbase + bk) * HID + bn);
            b1n = *reinterpret_cast<const float4*>(W + (size_t)(kbase + bk) * HID + bn + 4);
        }

        #pragma unroll
        for (int k = 0; k < 8; k++) {
            float a[8], b[8];
            *reinterpret_cast<float4*>(a)     = *reinterpret_cast<const float4*>(&As[cur][k][tm * 8]);
            *reinterpret_cast<float4*>(a + 4) = *reinterpret_cast<const float4*>(&As[cur][k][tm * 8 + 4]);
            *reinterpret_cast<float4*>(b)     = *reinterpret_cast<const float4*>(&Bs[cur][k][tn * 8]);
            *reinterpret_cast<float4*>(b + 4) = *reinterpret_cast<const float4*>(&Bs[cur][k][tn * 8 + 4]);
            #pragma unroll
            for (int i = 0; i < 8; i++)
                #pragma unroll
                for (int j = 0; j < 8; j++)
                    acc[i][j] = fmaf(a[i], b[j], acc[i][j]);
        }

        if (has_next) {
            As[nxt][ak][am] = a_n.x; As[nxt][ak + 1][am] = a_n.y;
            *reinterpret_cast<float4*>(&Bs[nxt][bk][bn])     = b0n;
            *reinterpret_cast<float4*>(&Bs[nxt][bk][bn + 4]) = b1n;
        }
        __syncthreads();
    }

    // epilogue: silu + store
    #pragma unroll
    for (int i = 0; i < 8; i++) {
        int m = tm * 8 + i;
        if (m < mcount) {
            float* crow = C + (size_t)(row0 + m) * HID + tn * 8;
            float4 v0, v1;
            v0.x = silu(acc[i][0]); v0.y = silu(acc[i][1]);
            v0.z = silu(acc[i][2]); v0.w = silu(acc[i][3]);
            v1.x = silu(acc[i][4]); v1.y = silu(acc[i][5]);
            v1.z = silu(acc[i][6]); v1.w = silu(acc[i][7]);
            *reinterpret_cast<float4*>(crow)     = v0;
            *reinterpret_cast<float4*>(crow + 4) = v1;
        }
    }
}

// ---------------- K8: final projection + per-structure sum ----------------
__global__ void out_kernel(const float* __restrict__ W3,
                           const int* __restrict__ numbers,
                           const int* __restrict__ batch,
                           float* __restrict__ out) {
    int row  = blockIdx.x * 8 + (threadIdx.x >> 5);
    int lane = threadIdx.x & 31;
    if (row >= N_ATOMS) return;
    int a = g_sorted[row];
    int s = numbers[a];
    const float* h = g_h2 + (size_t)row * HID;
    const float* w = W3 + (size_t)s * HID;
    float sum = 0.f;
    #pragma unroll
    for (int k = lane; k < HID; k += 32)
        sum = fmaf(h[k], w[k], sum);
    #pragma unroll
    for (int o = 16; o > 0; o >>= 1)
        sum += __shfl_xor_sync(0xFFFFFFFFu, sum, o);
    if (lane == 0)
        atomicAdd(&out[batch[a]], sum);   // SCALE = 1.0
}

// ---------------- launch ----------------
extern "C" void kernel_launch(void* const* d_in, const int* in_sizes, int n_in,
                              void* d_out, int out_size) {
    const float* positions    = (const float*)d_in[0];
    const float* cells        = (const float*)d_in[1];
    const int*   numbers      = (const int*)  d_in[2];
    const int*   edge_indices = (const int*)  d_in[3];
    const int*   edge_offsets = (const int*)  d_in[4];
    const int*   batch        = (const int*)  d_in[5];
    const float* Wc           = (const float*)d_in[6];
    const float* W1           = (const float*)d_in[7];
    const float* W2           = (const float*)d_in[8];
    const float* W3           = (const float*)d_in[9];
    float* out = (float*)d_out;

    // exact cover of g_c in float4s: 20000*512/4 = 2,560,000 = 10000 * 256
    zero_kernel<<<10000, 256>>>(out);
    atom_prep_kernel<<<(N_ATOMS + 255) / 256, 256>>>(numbers, batch, Wc, out);
    offsets_kernel<<<1, 32>>>();
    scatter_kernel<<<(N_ATOMS + 255) / 256, 256>>>(numbers);
    edge_kernel<<<N_EDGES / 256, 256>>>(positions, cells, numbers,
                                        edge_indices, edge_offsets, batch);
    ps_kernel<<<N_ATOMS, 128>>>();

    dim3 g1((N_ATOMS + 63) / 64, N_SPECIES);
    gemm_kernel<1><<<g1, 256>>>(W1, PS_DIM);
    gemm_kernel<2><<<g1, 256>>>(W2, HID);
    out_kernel<<<(N_ATOMS + 7) / 8, 256>>>(W3, numbers, batch, out);
}

// round 2
// speedup vs baseline: 1.6826x; 1.6826x over previous
#include <cuda_runtime.h>
#include <math.h>
#include <stdint.h>

// ---------------- problem constants ----------------
#define N_ATOMS   20000
#define N_EDGES   640000
#define N_STRUCT  100
#define N_SPECIES 4
#define N_RADIAL  8
#define N_SPH     16
#define Q_DIM     32                // N_SPECIES * N_RADIAL
#define C_PER_ATOM 512              // Q_DIM * N_SPH
#define PS_DIM    4096              // (L_MAX+1) * Q * Q  (full, for W1 indexing)
#define NPAIR     528               // Q*(Q+1)/2
#define PS_SYM    2112              // (L_MAX+1) * NPAIR
#define HID       256
#define CUTOFF    5.0f
#define EPSR      1e-12f

// ---------------- scratch (static device globals; no allocation) ----------------
__device__ float g_c  [(size_t)N_ATOMS * C_PER_ATOM];        // 41 MB
__device__ float g_ps [(size_t)N_ATOMS * PS_SYM];            // 169 MB
__device__ float g_h1 [(size_t)N_ATOMS * HID];               // 20.5 MB
__device__ float g_h2 [(size_t)N_ATOMS * HID];               // 20.5 MB
__device__ float g_w1s[(size_t)N_SPECIES * PS_SYM * HID];    // 8.6 MB folded W1
__device__ int   g_pairq[NPAIR];
__device__ int   g_pairp[NPAIR];
__device__ int   g_counts[N_SPECIES];
__device__ int   g_off[N_SPECIES];
__device__ int   g_cursor[N_SPECIES];
__device__ int   g_sorted[N_ATOMS];

// ---------------- helpers ----------------
__device__ __forceinline__ void red4(float* p, float a, float b, float c, float d) {
    asm volatile("red.global.add.v4.f32 [%0], {%1,%2,%3,%4};"
                 :: "l"(p), "f"(a), "f"(b), "f"(c), "f"(d) : "memory");
}

__device__ __forceinline__ float silu(float x) {
    return x / (1.0f + expf(-x));
}

// ---------------- K0: zero scratch + output + counters ----------------
__global__ void zero_kernel(float* __restrict__ out) {
    size_t idx = (size_t)blockIdx.x * blockDim.x + threadIdx.x;
    float4* c4 = reinterpret_cast<float4*>(g_c);
    c4[idx] = make_float4(0.f, 0.f, 0.f, 0.f);
    if (idx < N_STRUCT) out[idx] = 0.f;
    if (idx < N_SPECIES) g_counts[idx] = 0;
}

// ---------------- K1: composition energy + species histogram ----------------
__global__ void atom_prep_kernel(const int* __restrict__ numbers,
                                 const int* __restrict__ batch,
                                 const float* __restrict__ Wc,
                                 float* __restrict__ out) {
    int a = blockIdx.x * blockDim.x + threadIdx.x;
    if (a >= N_ATOMS) return;
    int s = numbers[a];
    atomicAdd(&g_counts[s], 1);
    atomicAdd(&out[batch[a]], Wc[s]);
}

// ---------------- K2: exclusive scan over species counts + pair table ----------------
__global__ void offsets_kernel() {
    int t = threadIdx.x;
    if (t == 0) {
        int acc = 0;
        for (int s = 0; s < N_SPECIES; s++) {
            g_off[s] = acc;
            g_cursor[s] = acc;
            acc += g_counts[s];
        }
    }
    // build (q<=p) pair table: idx order q-major
    for (int i = t; i < NPAIR; i += blockDim.x) {
        int q = 0, off = 0;
        while (off + (Q_DIM - q) <= i) { off += Q_DIM - q; q++; }
        g_pairq[i] = q;
        g_pairp[i] = q + (i - off);
    }
}

// ---------------- K3: scatter atoms into species-sorted order ----------------
__global__ void scatter_kernel(const int* __restrict__ numbers) {
    int a = blockIdx.x * blockDim.x + threadIdx.x;
    if (a >= N_ATOMS) return;
    int s = numbers[a];
    int pos = atomicAdd(&g_cursor[s], 1);
    g_sorted[pos] = a;
}

// ---------------- K3b: fold W1 over (q,p) symmetry -> g_w1s ----------------
__global__ void fold_kernel(const float* __restrict__ W1) {
    const int total = N_SPECIES * PS_SYM * HID;
    for (int i = blockIdx.x * blockDim.x + threadIdx.x; i < total;
         i += gridDim.x * blockDim.x) {
        int h    = i & (HID - 1);
        int rest = i >> 8;                 // /HID
        int row  = rest % PS_SYM;
        int s    = rest / PS_SYM;
        int l    = row / NPAIR;
        int pr   = row - l * NPAIR;
        int q = g_pairq[pr], p = g_pairp[pr];
        const float* Ws = W1 + (size_t)s * PS_DIM * HID;
        float v = Ws[(size_t)(l * 1024 + q * 32 + p) * HID + h];
        if (q != p)
            v += Ws[(size_t)(l * 1024 + p * 32 + q) * HID + h];
        g_w1s[i] = v;
    }
}

// ---------------- K4: edge featurization + segment reduction into g_c ----------------
__global__ void edge_kernel(const float* __restrict__ pos,
                            const float* __restrict__ cells,
                            const int* __restrict__ numbers,
                            const int* __restrict__ ei,
                            const int* __restrict__ eoff,
                            const int* __restrict__ batch) {
    int e = blockIdx.x * blockDim.x + threadIdx.x;
    if (e >= N_EDGES) return;
    int i = ei[e];
    int j = ei[N_EDGES + e];

    float pix = pos[3*i+0], piy = pos[3*i+1], piz = pos[3*i+2];
    float pjx = pos[3*j+0], pjy = pos[3*j+1], pjz = pos[3*j+2];

    int o0 = eoff[3*e+0], o1 = eoff[3*e+1], o2 = eoff[3*e+2];
    float sx = 0.f, sy = 0.f, sz = 0.f;
    if (o0 | o1 | o2) {
        int b = batch[i];
        const float* cb = cells + (size_t)b * 9;
        float f0 = (float)o0, f1 = (float)o1, f2 = (float)o2;
        sx = f0*cb[0] + f1*cb[3] + f2*cb[6];
        sy = f0*cb[1] + f1*cb[4] + f2*cb[7];
        sz = f0*cb[2] + f1*cb[5] + f2*cb[8];
    }

    float dx = pjx - pix + sx;
    float dy = pjy - piy + sy;
    float dz = pjz - piz + sz;
    float r2 = dx*dx + dy*dy + dz*dz + EPSR;
    float r  = sqrtf(r2);
    if (r >= CUTOFF) return;

    float inv = 1.0f / r;
    float a_c = r * (1.0f / CUTOFF);
    float fc  = 0.5f * (cospif(a_c) + 1.0f);
    float x = dx * inv, y = dy * inv, z = dz * inv;
    float x2 = x*x, y2 = y*y, z2 = z*z;

    float Y[16];
    Y[0]  = 0.28209479177387814f;
    Y[1]  = 0.4886025119029199f * y;
    Y[2]  = 0.4886025119029199f * z;
    Y[3]  = 0.4886025119029199f * x;
    Y[4]  = 1.0925484305920792f * x * y;
    Y[5]  = 1.0925484305920792f * y * z;
    Y[6]  = 0.31539156525252005f * (3.0f*z2 - 1.0f);
    Y[7]  = 1.0925484305920792f * x * z;
    Y[8]  = 0.5462742152960396f * (x2 - y2);
    Y[9]  = 0.5900435899266435f * y * (3.0f*x2 - y2);
    Y[10] = 2.890611442640554f  * x * y * z;
    Y[11] = 0.4570457994644658f * y * (5.0f*z2 - 1.0f);
    Y[12] = 0.3731763325901154f * z * (5.0f*z2 - 3.0f);
    Y[13] = 0.4570457994644658f * x * (5.0f*z2 - 1.0f);
    Y[14] = 1.445305721320277f  * z * (x2 - y2);
    Y[15] = 0.5900435899266435f * x * (x2 - 3.0f*y2);

    float rn[N_RADIAL];
    float scale = inv * fc;
    #pragma unroll
    for (int n = 0; n < N_RADIAL; n++)
        rn[n] = sinpif((float)(n + 1) * a_c) * scale;

    int sj = numbers[j];
    float* base = g_c + ((size_t)i * N_SPECIES + sj) * (N_RADIAL * N_SPH);

    #pragma unroll
    for (int n = 0; n < N_RADIAL; n++) {
        float rv = rn[n];
        #pragma unroll
        for (int m4 = 0; m4 < 4; m4++) {
            red4(base + n*16 + m4*4,
                 rv * Y[m4*4 + 0], rv * Y[m4*4 + 1],
                 rv * Y[m4*4 + 2], rv * Y[m4*4 + 3]);
        }
    }
}

// ---------------- K5: symmetric-packed power spectrum per atom ----------------
__global__ void ps_kernel() {
    __shared__ float cs[C_PER_ATOM];
    __shared__ int   pq[NPAIR];
    __shared__ int   pp[NPAIR];
    int a = blockIdx.x;
    int t = threadIdx.x;      // 128 threads
    const float4* ca = reinterpret_cast<const float4*>(g_c + (size_t)a * C_PER_ATOM);
    reinterpret_cast<float4*>(cs)[t] = ca[t];
    for (int i = t; i < NPAIR; i += 128) {
        pq[i] = g_pairq[i];
        pp[i] = g_pairp[i];
    }
    __syncthreads();

    const float norm[4] = {1.0f, 0.5773502691896258f, 0.4472135954999579f, 0.3779644730092272f};
    float* outp = g_ps + (size_t)a * PS_SYM;

    #pragma unroll
    for (int w = 0; w < 17; w++) {
        int idx = w * 128 + t;            // 0..2111
        if (idx >= PS_SYM) break;
        int l  = idx / NPAIR;
        int pr = idx - l * NPAIR;
        int q = pq[pr], p = pp[pr];
        int m0 = l * l;
        int m1 = (l + 1) * (l + 1);
        float sum = 0.f;
        for (int m = m0; m < m1; m++)
            sum += cs[q * 16 + m] * cs[p * 16 + m];
        outp[idx] = sum * norm[l];
    }
}

// ---------------- K6/K7: species-grouped SGEMM  (M-tile 64, N=256, K-tile 8) ----------------
// WHICH==1: A=g_ps (gathered rows, K=PS_SYM), W=g_w1s, C=g_h1.
// WHICH==2: A=g_h1, W=W2 (K=HID), C=g_h2.
template<int WHICH>
__global__ void __launch_bounds__(256) gemm_kernel(const float* __restrict__ Wbase, int K) {
    const int s    = blockIdx.y;
    const int mloc = blockIdx.x * 64;
    const int count = g_counts[s];
    if (mloc >= count) return;
    const int row0   = g_off[s] + mloc;
    const int mcount = min(64, count - mloc);
    const float* W = ((WHICH == 1) ? (const float*)g_w1s : Wbase) + (size_t)s * K * HID;

    const float* A = (WHICH == 1) ? g_ps : g_h1;
    float*       C = (WHICH == 1) ? g_h1 : g_h2;

    __shared__ float As[2][8][64];
    __shared__ float Bs[2][8][256];

    const int t  = threadIdx.x;
    const int tm = t >> 5;          // 0..7
    const int tn = t & 31;          // 0..31

    const int am = t >> 2;          // 0..63
    const int ak = (t & 3) * 2;     // 0,2,4,6
    const bool avalid = (am < mcount);
    const float* Arow = A;
    if (avalid) {
        int r = row0 + am;
        int src = (WHICH == 1) ? g_sorted[r] : r;
        Arow = A + (size_t)src * K;
    }
    const int bk = t >> 5;          // 0..7
    const int bn = (t & 31) * 8;    // 0..248

    float acc[8][8];
    #pragma unroll
    for (int i = 0; i < 8; i++)
        #pragma unroll
        for (int j = 0; j < 8; j++) acc[i][j] = 0.f;

    const int NT = K >> 3;

    {
        float2 ar = avalid ? *reinterpret_cast<const float2*>(Arow + ak)
                           : make_float2(0.f, 0.f);
        float4 b0 = *reinterpret_cast<const float4*>(W + (size_t)bk * HID + bn);
        float4 b1 = *reinterpret_cast<const float4*>(W + (size_t)bk * HID + bn + 4);
        As[0][ak][am] = ar.x; As[0][ak + 1][am] = ar.y;
        *reinterpret_cast<float4*>(&Bs[0][bk][bn])     = b0;
        *reinterpret_cast<float4*>(&Bs[0][bk][bn + 4]) = b1;
    }
    __syncthreads();

    for (int kt = 0; kt < NT; kt++) {
        const int cur = kt & 1, nxt = cur ^ 1;
        const bool has_next = (kt + 1 < NT);

        float2 a_n = make_float2(0.f, 0.f);
        float4 b0n, b1n;
        if (has_next) {
            int kbase = (kt + 1) * 8;
            if (avalid) a_n = *reinterpret_cast<const float2*>(Arow + kbase + ak);
            b0n = *reinterpret_cast<const float4*>(W + (size_t)(kbase + bk) * HID + bn);
            b1n = *reinterpret_cast<const float4*>(W + (size_t)(kbase + bk) * HID + bn + 4);
        }

        #pragma unroll
        for (int k = 0; k < 8; k++) {
            float a[8], b[8];
            *reinterpret_cast<float4*>(a)     = *reinterpret_cast<const float4*>(&As[cur][k][tm * 8]);
            *reinterpret_cast<float4*>(a + 4) = *reinterpret_cast<const float4*>(&As[cur][k][tm * 8 + 4]);
            *reinterpret_cast<float4*>(b)     = *reinterpret_cast<const float4*>(&Bs[cur][k][tn * 8]);
            *reinterpret_cast<float4*>(b + 4) = *reinterpret_cast<const float4*>(&Bs[cur][k][tn * 8 + 4]);
            #pragma unroll
            for (int i = 0; i < 8; i++)
                #pragma unroll
                for (int j = 0; j < 8; j++)
                    acc[i][j] = fmaf(a[i], b[j], acc[i][j]);
        }

        if (has_next) {
            As[nxt][ak][am] = a_n.x; As[nxt][ak + 1][am] = a_n.y;
            *reinterpret_cast<float4*>(&Bs[nxt][bk][bn])     = b0n;
            *reinterpret_cast<float4*>(&Bs[nxt][bk][bn + 4]) = b1n;
        }
        __syncthreads();
    }

    #pragma unroll
    for (int i = 0; i < 8; i++) {
        int m = tm * 8 + i;
        if (m < mcount) {
            float* crow = C + (size_t)(row0 + m) * HID + tn * 8;
            float4 v0, v1;
            v0.x = silu(acc[i][0]); v0.y = silu(acc[i][1]);
            v0.z = silu(acc[i][2]); v0.w = silu(acc[i][3]);
            v1.x = silu(acc[i][4]); v1.y = silu(acc[i][5]);
            v1.z = silu(acc[i][6]); v1.w = silu(acc[i][7]);
            *reinterpret_cast<float4*>(crow)     = v0;
            *reinterpret_cast<float4*>(crow + 4) = v1;
        }
    }
}

// ---------------- K8: final projection + per-structure sum ----------------
__global__ void out_kernel(const float* __restrict__ W3,
                           const int* __restrict__ numbers,
                           const int* __restrict__ batch,
                           float* __restrict__ out) {
    int row  = blockIdx.x * 8 + (threadIdx.x >> 5);
    int lane = threadIdx.x & 31;
    if (row >= N_ATOMS) return;
    int a = g_sorted[row];
    int s = numbers[a];
    const float* h = g_h2 + (size_t)row * HID;
    const float* w = W3 + (size_t)s * HID;
    float sum = 0.f;
    #pragma unroll
    for (int k = lane; k < HID; k += 32)
        sum = fmaf(h[k], w[k], sum);
    #pragma unroll
    for (int o = 16; o > 0; o >>= 1)
        sum += __shfl_xor_sync(0xFFFFFFFFu, sum, o);
    if (lane == 0)
        atomicAdd(&out[batch[a]], sum);   // SCALE = 1.0
}

// ---------------- launch ----------------
extern "C" void kernel_launch(void* const* d_in, const int* in_sizes, int n_in,
                              void* d_out, int out_size) {
    const float* positions    = (const float*)d_in[0];
    const float* cells        = (const float*)d_in[1];
    const int*   numbers      = (const int*)  d_in[2];
    const int*   edge_indices = (const int*)  d_in[3];
    const int*   edge_offsets = (const int*)  d_in[4];
    const int*   batch        = (const int*)  d_in[5];
    const float* Wc           = (const float*)d_in[6];
    const float* W1           = (const float*)d_in[7];
    const float* W2           = (const float*)d_in[8];
    const float* W3           = (const float*)d_in[9];
    float* out = (float*)d_out;

    zero_kernel<<<10000, 256>>>(out);                       // covers g_c exactly
    atom_prep_kernel<<<(N_ATOMS + 255) / 256, 256>>>(numbers, batch, Wc, out);
    offsets_kernel<<<1, 256>>>();                           // scan + pair table
    scatter_kernel<<<(N_ATOMS + 255) / 256, 256>>>(numbers);
    fold_kernel<<<2048, 256>>>(W1);                         // W1 -> g_w1s (needs pair table)
    edge_kernel<<<N_EDGES / 256, 256>>>(positions, cells, numbers,
                                        edge_indices, edge_offsets, batch);
    ps_kernel<<<N_ATOMS, 128>>>();

    dim3 g1((N_ATOMS + 63) / 64, N_SPECIES);
    gemm_kernel<1><<<g1, 256>>>(nullptr, PS_SYM);
    gemm_kernel<2><<<g1, 256>>>(W2, HID);
    out_kernel<<<(N_ATOMS + 7) / 8, 256>>>(W3, numbers, batch, out);
}

// round 4
// speedup vs baseline: 2.9488x; 1.7525x over previous
#include <cuda_runtime.h>
#include <cuda_bf16.h>
#include <math.h>
#include <stdint.h>

// ---------------- problem constants ----------------
#define N_ATOMS   20000
#define N_EDGES   640000
#define N_STRUCT  100
#define N_SPECIES 4
#define N_RADIAL  8
#define N_SPH     16
#define Q_DIM     32
#define C_PER_ATOM 512
#define PS_DIM    4096
#define NPAIR     528
#define PS_SYM    2112              // 33 * 64
#define HID       256
#define CUTOFF    5.0f
#define EPSR      1e-12f
#define MAX_TILES 160

// ---------------- scratch ----------------
__device__ float g_c  [(size_t)N_ATOMS * C_PER_ATOM];
__device__ float g_ps [(size_t)N_ATOMS * PS_SYM];
__device__ float g_h1 [(size_t)N_ATOMS * HID];
__device__ float g_h2 [(size_t)N_ATOMS * HID];
__device__ __nv_bfloat16 g_w1h[(size_t)N_SPECIES * HID * PS_SYM];  // W1s^T hi
__device__ __nv_bfloat16 g_w1l[(size_t)N_SPECIES * HID * PS_SYM];  // lo
__device__ __nv_bfloat16 g_w2h[(size_t)N_SPECIES * HID * HID];
__device__ __nv_bfloat16 g_w2l[(size_t)N_SPECIES * HID * HID];
__device__ int   g_pairq[NPAIR];
__device__ int   g_pairp[NPAIR];
__device__ int   g_counts[N_SPECIES];
__device__ int   g_off[N_SPECIES];
__device__ int   g_cursor[N_SPECIES];
__device__ int   g_sorted[N_ATOMS];

// ---------------- helpers ----------------
__device__ __forceinline__ float silu(float x) { return x / (1.0f + expf(-x)); }

__device__ __forceinline__ void red4(float* p, float a, float b, float c, float d) {
    asm volatile("red.global.add.v4.f32 [%0], {%1,%2,%3,%4};"
                 :: "l"(p), "f"(a), "f"(b), "f"(c), "f"(d) : "memory");
}

__device__ __forceinline__ uint32_t pack2(__nv_bfloat16 a, __nv_bfloat16 b) {
    return (uint32_t)__bfloat16_as_ushort(a) | ((uint32_t)__bfloat16_as_ushort(b) << 16);
}

__device__ __forceinline__ void mma_bf16(float& c0, float& c1, float& c2, float& c3,
                                         uint32_t a0, uint32_t a1, uint32_t a2, uint32_t a3,
                                         uint32_t b0, uint32_t b1) {
    asm volatile("mma.sync.aligned.m16n8k16.row.col.f32.bf16.bf16.f32 "
                 "{%0,%1,%2,%3}, {%4,%5,%6,%7}, {%8,%9}, {%0,%1,%2,%3};"
                 : "+f"(c0), "+f"(c1), "+f"(c2), "+f"(c3)
                 : "r"(a0), "r"(a1), "r"(a2), "r"(a3), "r"(b0), "r"(b1));
}

// ---------------- K0: zero ----------------
__global__ void zero_kernel(float* __restrict__ out) {
    size_t idx = (size_t)blockIdx.x * blockDim.x + threadIdx.x;
    float4* c4 = reinterpret_cast<float4*>(g_c);
    c4[idx] = make_float4(0.f, 0.f, 0.f, 0.f);
    if (idx < N_STRUCT) out[idx] = 0.f;
    if (idx < N_SPECIES) g_counts[idx] = 0;
}

// ---------------- K1 ----------------
__global__ void atom_prep_kernel(const int* __restrict__ numbers,
                                 const int* __restrict__ batch,
                                 const float* __restrict__ Wc,
                                 float* __restrict__ out) {
    int a = blockIdx.x * blockDim.x + threadIdx.x;
    if (a >= N_ATOMS) return;
    int s = numbers[a];
    atomicAdd(&g_counts[s], 1);
    atomicAdd(&out[batch[a]], Wc[s]);
}

// ---------------- K2 ----------------
__global__ void offsets_kernel() {
    int t = threadIdx.x;
    if (t == 0) {
        int acc = 0;
        for (int s = 0; s < N_SPECIES; s++) {
            g_off[s] = acc;
            g_cursor[s] = acc;
            acc += g_counts[s];
        }
    }
    for (int i = t; i < NPAIR; i += blockDim.x) {
        int q = 0, off = 0;
        while (off + (Q_DIM - q) <= i) { off += Q_DIM - q; q++; }
        g_pairq[i] = q;
        g_pairp[i] = q + (i - off);
    }
}

// ---------------- K3 ----------------
__global__ void scatter_kernel(const int* __restrict__ numbers) {
    int a = blockIdx.x * blockDim.x + threadIdx.x;
    if (a >= N_ATOMS) return;
    int s = numbers[a];
    int pos = atomicAdd(&g_cursor[s], 1);
    g_sorted[pos] = a;
}

// ---------------- K3b: fold W1 (symmetry) + transpose + bf16 hi/lo split ----------------
__global__ void fold_w1_kernel(const float* __restrict__ W1) {
    const int total = N_SPECIES * HID * PS_SYM;
    for (int i = blockIdx.x * blockDim.x + threadIdx.x; i < total;
         i += gridDim.x * blockDim.x) {
        int k    = i % PS_SYM;
        int rest = i / PS_SYM;
        int n    = rest & (HID - 1);
        int s    = rest >> 8;
        int l    = k / NPAIR;
        int pr   = k - l * NPAIR;
        int q = g_pairq[pr], p = g_pairp[pr];
        const float* Ws = W1 + (size_t)s * PS_DIM * HID;
        float v = Ws[(size_t)(l * 1024 + q * 32 + p) * HID + n];
        if (q != p)
            v += Ws[(size_t)(l * 1024 + p * 32 + q) * HID + n];
        __nv_bfloat16 h = __float2bfloat16_rn(v);
        __nv_bfloat16 lo = __float2bfloat16_rn(v - __bfloat162float(h));
        g_w1h[i] = h;
        g_w1l[i] = lo;
    }
}

// ---------------- K3c: W2 transpose + split ----------------
__global__ void fold_w2_kernel(const float* __restrict__ W2) {
    const int total = N_SPECIES * HID * HID;
    for (int i = blockIdx.x * blockDim.x + threadIdx.x; i < total;
         i += gridDim.x * blockDim.x) {
        int k    = i & (HID - 1);
        int rest = i >> 8;
        int n    = rest & (HID - 1);
        int s    = rest >> 8;
        float v = W2[((size_t)(s * HID + k)) * HID + n];
        __nv_bfloat16 h = __float2bfloat16_rn(v);
        __nv_bfloat16 lo = __float2bfloat16_rn(v - __bfloat162float(h));
        g_w2h[i] = h;
        g_w2l[i] = lo;
    }
}

// ---------------- K4: edge featurization ----------------
__global__ void edge_kernel(const float* __restrict__ pos,
                            const float* __restrict__ cells,
                            const int* __restrict__ numbers,
                            const int* __restrict__ ei,
                            const int* __restrict__ eoff,
                            const int* __restrict__ batch) {
    int e = blockIdx.x * blockDim.x + threadIdx.x;
    if (e >= N_EDGES) return;
    int i = ei[e];
    int j = ei[N_EDGES + e];

    float pix = pos[3*i+0], piy = pos[3*i+1], piz = pos[3*i+2];
    float pjx = pos[3*j+0], pjy = pos[3*j+1], pjz = pos[3*j+2];

    int o0 = eoff[3*e+0], o1 = eoff[3*e+1], o2 = eoff[3*e+2];
    float sx = 0.f, sy = 0.f, sz = 0.f;
    if (o0 | o1 | o2) {
        int b = batch[i];
        const float* cb = cells + (size_t)b * 9;
        float f0 = (float)o0, f1 = (float)o1, f2 = (float)o2;
        sx = f0*cb[0] + f1*cb[3] + f2*cb[6];
        sy = f0*cb[1] + f1*cb[4] + f2*cb[7];
        sz = f0*cb[2] + f1*cb[5] + f2*cb[8];
    }

    float dx = pjx - pix + sx;
    float dy = pjy - piy + sy;
    float dz = pjz - piz + sz;
    float r2 = dx*dx + dy*dy + dz*dz + EPSR;
    float r  = sqrtf(r2);
    if (r >= CUTOFF) return;

    float inv = 1.0f / r;
    float a_c = r * (1.0f / CUTOFF);
    float fc  = 0.5f * (cospif(a_c) + 1.0f);
    float x = dx * inv, y = dy * inv, z = dz * inv;
    float x2 = x*x, y2 = y*y, z2 = z*z;

    float Y[16];
    Y[0]  = 0.28209479177387814f;
    Y[1]  = 0.4886025119029199f * y;
    Y[2]  = 0.4886025119029199f * z;
    Y[3]  = 0.4886025119029199f * x;
    Y[4]  = 1.0925484305920792f * x * y;
    Y[5]  = 1.0925484305920792f * y * z;
    Y[6]  = 0.31539156525252005f * (3.0f*z2 - 1.0f);
    Y[7]  = 1.0925484305920792f * x * z;
    Y[8]  = 0.5462742152960396f * (x2 - y2);
    Y[9]  = 0.5900435899266435f * y * (3.0f*x2 - y2);
    Y[10] = 2.890611442640554f  * x * y * z;
    Y[11] = 0.4570457994644658f * y * (5.0f*z2 - 1.0f);
    Y[12] = 0.3731763325901154f * z * (5.0f*z2 - 3.0f);
    Y[13] = 0.4570457994644658f * x * (5.0f*z2 - 1.0f);
    Y[14] = 1.445305721320277f  * z * (x2 - y2);
    Y[15] = 0.5900435899266435f * x * (x2 - 3.0f*y2);

    float rn[N_RADIAL];
    float scale = inv * fc;
    #pragma unroll
    for (int n = 0; n < N_RADIAL; n++)
        rn[n] = sinpif((float)(n + 1) * a_c) * scale;

    int sj = numbers[j];
    float* base = g_c + ((size_t)i * N_SPECIES + sj) * (N_RADIAL * N_SPH);

    #pragma unroll
    for (int n = 0; n < N_RADIAL; n++) {
        float rv = rn[n];
        #pragma unroll
        for (int m4 = 0; m4 < 4; m4++) {
            red4(base + n*16 + m4*4,
                 rv * Y[m4*4 + 0], rv * Y[m4*4 + 1],
                 rv * Y[m4*4 + 2], rv * Y[m4*4 + 3]);
        }
    }
}

// ---------------- K5: symmetric-packed power spectrum ----------------
__global__ void ps_kernel() {
    __shared__ float cs[C_PER_ATOM];
    __shared__ int   pq[NPAIR];
    __shared__ int   pp[NPAIR];
    int a = blockIdx.x;
    int t = threadIdx.x;      // 128
    const float4* ca = reinterpret_cast<const float4*>(g_c + (size_t)a * C_PER_ATOM);
    reinterpret_cast<float4*>(cs)[t] = ca[t];
    for (int i = t; i < NPAIR; i += 128) {
        pq[i] = g_pairq[i];
        pp[i] = g_pairp[i];
    }
    __syncthreads();

    const float norm[4] = {1.0f, 0.5773502691896258f, 0.4472135954999579f, 0.3779644730092272f};
    float* outp = g_ps + (size_t)a * PS_SYM;

    #pragma unroll
    for (int w = 0; w < 17; w++) {
        int idx = w * 128 + t;
        if (idx >= PS_SYM) break;
        int l  = idx / NPAIR;
        int pr = idx - l * NPAIR;
        int q = pq[pr], p = pp[pr];
        int m0 = l * l;
        int m1 = (l + 1) * (l + 1);
        float sum = 0.f;
        for (int m = m0; m < m1; m++)
            sum += cs[q * 16 + m] * cs[p * 16 + m];
        outp[idx] = sum * norm[l];
    }
}

// ---------------- K6/K7: mma.sync bf16x3-split GEMM ----------------
// CTA tile: M=128 x N=128 (half of HID per blockIdx parity).
// SMEM per stage: A[128][72] bf16 (cols 0..31 = hi, 32..63 = lo),
//                 B[128][72] bf16 (same split). Double buffered.
// Per source-K chunk of 32, compute 3 combos x 2 k16 steps:
//   (Ahi,Bhi), (Alo,Bhi), (Ahi,Blo).
#define KPAD 72
#define STAGE_BF16 (128 * KPAD)            // per matrix
#define STAGE_BYTES (STAGE_BF16 * 2 * 2)   // A + B = 36864
#define GEMM_SMEM (2 * STAGE_BYTES)        // 73728

template<int WHICH>
__global__ void __launch_bounds__(256) gemm_mma_kernel() {
    constexpr int K  = (WHICH == 1) ? PS_SYM : HID;
    constexpr int NS = K / 32;

    const int item  = blockIdx.x;
    const int tile  = item >> 1;
    const int nbase = (item & 1) * 128;

    int s = -1, mloc = 0, acc = 0;
    #pragma unroll
    for (int sp = 0; sp < N_SPECIES; sp++) {
        int ts = (g_counts[sp] + 127) >> 7;
        if (s < 0 && tile < acc + ts) { s = sp; mloc = (tile - acc) << 7; }
        acc += ts;
    }
    if (s < 0) return;
    const int row0   = g_off[s] + mloc;
    const int mcount = min(128, g_counts[s] - mloc);

    extern __shared__ __nv_bfloat16 smem[];

    const int tid  = threadIdx.x;
    const int wid  = tid >> 5;
    const int lane = tid & 31;
    const int gid  = lane >> 2;      // 0..7
    const int tig  = lane & 3;       // 0..3
    const int wm   = wid & 1;        // 0..1 -> 64 rows
    const int wn   = wid >> 1;       // 0..3 -> 32 cols

    // loader mapping: row = tid>>1 (0..127), half = tid&1 (16 elems)
    const int lrow = tid >> 1;
    const int lh   = (tid & 1) * 16;
    const bool mvalid = (lrow < mcount);
    const float* Arow = nullptr;
    if (mvalid) {
        int r = row0 + lrow;
        int src = (WHICH == 1) ? g_sorted[r] : r;
        Arow = ((WHICH == 1) ? g_ps : g_h1) + (size_t)src * K;
    }
    const __nv_bfloat16* Bhrow =
        ((WHICH == 1) ? g_w1h : g_w2h) + ((size_t)(s * HID + nbase + lrow)) * K;
    const __nv_bfloat16* Blrow =
        ((WHICH == 1) ? g_w1l : g_w2l) + ((size_t)(s * HID + nbase + lrow)) * K;

    float accum[4][4][4];
    #pragma unroll
    for (int i = 0; i < 4; i++)
        #pragma unroll
        for (int j = 0; j < 4; j++)
            #pragma unroll
            for (int e = 0; e < 4; e++) accum[i][j][e] = 0.f;

    // staging registers
    float4 fA[4];
    uint4  vBh[2], vBl[2];

    auto load_stage = [&](int kt) {
        const int kb = kt * 32 + lh;
        if (mvalid) {
            const float4* src = reinterpret_cast<const float4*>(Arow + kb);
            fA[0] = src[0]; fA[1] = src[1]; fA[2] = src[2]; fA[3] = src[3];
        } else {
            fA[0] = fA[1] = fA[2] = fA[3] = make_float4(0.f, 0.f, 0.f, 0.f);
        }
        const uint4* bh = reinterpret_cast<const uint4*>(Bhrow + kb);
        const uint4* bl = reinterpret_cast<const uint4*>(Blrow + kb);
        vBh[0] = bh[0]; vBh[1] = bh[1];
        vBl[0] = bl[0]; vBl[1] = bl[1];
    };

    auto store_stage = [&](int buf) {
        __nv_bfloat16* As = smem + buf * 2 * STAGE_BF16;
        __nv_bfloat16* Bs = As + STAGE_BF16;
        const float* f = reinterpret_cast<const float*>(fA);
        uint32_t hiw[8], low[8];
        #pragma unroll
        for (int i = 0; i < 8; i++) {
            float v0 = f[2*i], v1 = f[2*i+1];
            __nv_bfloat16 h0 = __float2bfloat16_rn(v0);
            __nv_bfloat16 h1 = __float2bfloat16_rn(v1);
            hiw[i] = pack2(h0, h1);
            low[i] = pack2(__float2bfloat16_rn(v0 - __bfloat162float(h0)),
                           __float2bfloat16_rn(v1 - __bfloat162float(h1)));
        }
        uint4* dsthi = reinterpret_cast<uint4*>(As + lrow * KPAD + lh);
        dsthi[0] = make_uint4(hiw[0], hiw[1], hiw[2], hiw[3]);
        dsthi[1] = make_uint4(hiw[4], hiw[5], hiw[6], hiw[7]);
        uint4* dstlo = reinterpret_cast<uint4*>(As + lrow * KPAD + 32 + lh);
        dstlo[0] = make_uint4(low[0], low[1], low[2], low[3]);
        dstlo[1] = make_uint4(low[4], low[5], low[6], low[7]);
        uint4* bh = reinterpret_cast<uint4*>(Bs + lrow * KPAD + lh);
        bh[0] = vBh[0]; bh[1] = vBh[1];
        uint4* bl = reinterpret_cast<uint4*>(Bs + lrow * KPAD + 32 + lh);
        bl[0] = vBl[0]; bl[1] = vBl[1];
    };

    load_stage(0);
    store_stage(0);
    __syncthreads();

    for (int kt = 0; kt < NS; kt++) {
        const int buf = kt & 1;
        const bool has_next = (kt + 1 < NS);
        if (has_next) load_stage(kt + 1);

        const __nv_bfloat16* As = smem + buf * 2 * STAGE_BF16;
        const __nv_bfloat16* Bs = As + STAGE_BF16;
        const __nv_bfloat16* Ab = As + (wm * 64 + gid) * KPAD + 2 * tig;
        const __nv_bfloat16* Bb = Bs + (wn * 32 + gid) * KPAD + 2 * tig;

        // combos: (aoff, boff) in { (0,0), (32,0), (0,32) }
        #pragma unroll
        for (int combo = 0; combo < 3; combo++) {
            const int aoff = (combo == 1) ? 32 : 0;
            const int boff = (combo == 2) ? 32 : 0;
            #pragma unroll
            for (int kk = 0; kk < 2; kk++) {
                const int ka = aoff + kk * 16;
                const int kb = boff + kk * 16;
                uint32_t bfr[4][2];
                #pragma unroll
                for (int nt = 0; nt < 4; nt++) {
                    const __nv_bfloat16* bp = Bb + nt * 8 * KPAD + kb;
                    bfr[nt][0] = *reinterpret_cast<const uint32_t*>(bp);
                    bfr[nt][1] = *reinterpret_cast<const uint32_t*>(bp + 8);
                }
                #pragma unroll
                for (int mt = 0; mt < 4; mt++) {
                    const __nv_bfloat16* ap = Ab + mt * 16 * KPAD + ka;
                    uint32_t a0 = *reinterpret_cast<const uint32_t*>(ap);
                    uint32_t a1 = *reinterpret_cast<const uint32_t*>(ap + 8 * KPAD);
                    uint32_t a2 = *reinterpret_cast<const uint32_t*>(ap + 8);
                    uint32_t a3 = *reinterpret_cast<const uint32_t*>(ap + 8 * KPAD + 8);
                    #pragma unroll
                    for (int nt = 0; nt < 4; nt++) {
                        mma_bf16(accum[mt][nt][0], accum[mt][nt][1],
                                 accum[mt][nt][2], accum[mt][nt][3],
                                 a0, a1, a2, a3, bfr[nt][0], bfr[nt][1]);
                    }
                }
            }
        }

        if (has_next) store_stage(buf ^ 1);
        __syncthreads();
    }

    // epilogue: silu + store
    float* C = (WHICH == 1) ? g_h1 : g_h2;
    #pragma unroll
    for (int mt = 0; mt < 4; mt++) {
        int r0 = wm * 64 + mt * 16 + gid;
        int r1 = r0 + 8;
        #pragma unroll
        for (int nt = 0; nt < 4; nt++) {
            int col = nbase + wn * 32 + nt * 8 + 2 * tig;
            if (r0 < mcount) {
                float2 v; v.x = silu(accum[mt][nt][0]); v.y = silu(accum[mt][nt][1]);
                *reinterpret_cast<float2*>(&C[(size_t)(row0 + r0) * HID + col]) = v;
            }
            if (r1 < mcount) {
                float2 v; v.x = silu(accum[mt][nt][2]); v.y = silu(accum[mt][nt][3]);
                *reinterpret_cast<float2*>(&C[(size_t)(row0 + r1) * HID + col]) = v;
            }
        }
    }
}

// ---------------- K8: final projection + per-structure sum ----------------
__global__ void out_kernel(const float* __restrict__ W3,
                           const int* __restrict__ numbers,
                           const int* __restrict__ batch,
                           float* __restrict__ out) {
    int row  = blockIdx.x * 8 + (threadIdx.x >> 5);
    int lane = threadIdx.x & 31;
    if (row >= N_ATOMS) return;
    int a = g_sorted[row];
    int s = numbers[a];
    const float* h = g_h2 + (size_t)row * HID;
    const float* w = W3 + (size_t)s * HID;
    float sum = 0.f;
    #pragma unroll
    for (int k = lane; k < HID; k += 32)
        sum = fmaf(h[k], w[k], sum);
    #pragma unroll
    for (int o = 16; o > 0; o >>= 1)
        sum += __shfl_xor_sync(0xFFFFFFFFu, sum, o);
    if (lane == 0)
        atomicAdd(&out[batch[a]], sum);
}

// ---------------- launch ----------------
extern "C" void kernel_launch(void* const* d_in, const int* in_sizes, int n_in,
                              void* d_out, int out_size) {
    const float* positions    = (const float*)d_in[0];
    const float* cells        = (const float*)d_in[1];
    const int*   numbers      = (const int*)  d_in[2];
    const int*   edge_indices = (const int*)  d_in[3];
    const int*   edge_offsets = (const int*)  d_in[4];
    const int*   batch        = (const int*)  d_in[5];
    const float* Wc           = (const float*)d_in[6];
    const float* W1           = (const float*)d_in[7];
    const float* W2           = (const float*)d_in[8];
    const float* W3           = (const float*)d_in[9];
    float* out = (float*)d_out;

    cudaFuncSetAttribute(gemm_mma_kernel<1>,
                         cudaFuncAttributeMaxDynamicSharedMemorySize, GEMM_SMEM);
    cudaFuncSetAttribute(gemm_mma_kernel<2>,
                         cudaFuncAttributeMaxDynamicSharedMemorySize, GEMM_SMEM);

    zero_kernel<<<10000, 256>>>(out);
    atom_prep_kernel<<<(N_ATOMS + 255) / 256, 256>>>(numbers, batch, Wc, out);
    offsets_kernel<<<1, 256>>>();
    scatter_kernel<<<(N_ATOMS + 255) / 256, 256>>>(numbers);
    fold_w1_kernel<<<2048, 256>>>(W1);
    fold_w2_kernel<<<512, 256>>>(W2);
    edge_kernel<<<N_EDGES / 256, 256>>>(positions, cells, numbers,
                                        edge_indices, edge_offsets, batch);
    ps_kernel<<<N_ATOMS, 128>>>();

    gemm_mma_kernel<1><<<MAX_TILES * 2, 256, GEMM_SMEM>>>();
    gemm_mma_kernel<2><<<MAX_TILES * 2, 256, GEMM_SMEM>>>();
    out_kernel<<<(N_ATOMS + 7) / 8, 256>>>(W3, numbers, batch, out);
}

// round 5
// speedup vs baseline: 3.5106x; 1.1905x over previous
#include <cuda_runtime.h>
#include <cuda_bf16.h>
#include <math.h>
#include <stdint.h>

// ---------------- problem constants ----------------
#define N_ATOMS   20000
#define N_EDGES   640000
#define N_STRUCT  100
#define N_SPECIES 4
#define N_RADIAL  8
#define N_SPH     16
#define Q_DIM     32
#define C_PER_ATOM 512
#define PS_DIM    4096
#define NPAIR     528
#define PS_SYM    2112              // 33 * 64
#define HID       256
#define CUTOFF    5.0f
#define EPSR      1e-12f
#define MAX_TILES 160

// ---------------- scratch ----------------
__device__ float g_c  [(size_t)N_ATOMS * C_PER_ATOM];
__device__ float g_ps [(size_t)N_ATOMS * PS_SYM];
__device__ float g_h1 [(size_t)N_ATOMS * HID];
__device__ float g_h2 [(size_t)N_ATOMS * HID];
__device__ __nv_bfloat16 g_w1h[(size_t)N_SPECIES * HID * PS_SYM];  // W1s^T hi
__device__ __nv_bfloat16 g_w1l[(size_t)N_SPECIES * HID * PS_SYM];  // lo
__device__ __nv_bfloat16 g_w2h[(size_t)N_SPECIES * HID * HID];
__device__ __nv_bfloat16 g_w2l[(size_t)N_SPECIES * HID * HID];
__device__ int   g_pairq[NPAIR];
__device__ int   g_pairp[NPAIR];
__device__ int   g_counts[N_SPECIES];
__device__ int   g_off[N_SPECIES];
__device__ int   g_cursor[N_SPECIES];
__device__ int   g_sorted[N_ATOMS];

// ---------------- helpers ----------------
__device__ __forceinline__ float silu(float x) { return x / (1.0f + expf(-x)); }

__device__ __forceinline__ void red4(float* p, float a, float b, float c, float d) {
    asm volatile("red.global.add.v4.f32 [%0], {%1,%2,%3,%4};"
                 :: "l"(p), "f"(a), "f"(b), "f"(c), "f"(d) : "memory");
}

__device__ __forceinline__ uint32_t pack2(__nv_bfloat16 a, __nv_bfloat16 b) {
    return (uint32_t)__bfloat16_as_ushort(a) | ((uint32_t)__bfloat16_as_ushort(b) << 16);
}

__device__ __forceinline__ void mma_bf16(float& c0, float& c1, float& c2, float& c3,
                                         uint32_t a0, uint32_t a1, uint32_t a2, uint32_t a3,
                                         uint32_t b0, uint32_t b1) {
    asm volatile("mma.sync.aligned.m16n8k16.row.col.f32.bf16.bf16.f32 "
                 "{%0,%1,%2,%3}, {%4,%5,%6,%7}, {%8,%9}, {%0,%1,%2,%3};"
                 : "+f"(c0), "+f"(c1), "+f"(c2), "+f"(c3)
                 : "r"(a0), "r"(a1), "r"(a2), "r"(a3), "r"(b0), "r"(b1));
}

// ---------------- K0: zero ----------------
__global__ void zero_kernel(float* __restrict__ out) {
    size_t idx = (size_t)blockIdx.x * blockDim.x + threadIdx.x;
    float4* c4 = reinterpret_cast<float4*>(g_c);
    c4[idx] = make_float4(0.f, 0.f, 0.f, 0.f);
    if (idx < N_STRUCT) out[idx] = 0.f;
    if (idx < N_SPECIES) g_counts[idx] = 0;
}

// ---------------- K1 ----------------
__global__ void atom_prep_kernel(const int* __restrict__ numbers,
                                 const int* __restrict__ batch,
                                 const float* __restrict__ Wc,
                                 float* __restrict__ out) {
    int a = blockIdx.x * blockDim.x + threadIdx.x;
    if (a >= N_ATOMS) return;
    int s = numbers[a];
    atomicAdd(&g_counts[s], 1);
    atomicAdd(&out[batch[a]], Wc[s]);
}

// ---------------- K2 ----------------
__global__ void offsets_kernel() {
    int t = threadIdx.x;
    if (t == 0) {
        int acc = 0;
        for (int s = 0; s < N_SPECIES; s++) {
            g_off[s] = acc;
            g_cursor[s] = acc;
            acc += g_counts[s];
        }
    }
    for (int i = t; i < NPAIR; i += blockDim.x) {
        int q = 0, off = 0;
        while (off + (Q_DIM - q) <= i) { off += Q_DIM - q; q++; }
        g_pairq[i] = q;
        g_pairp[i] = q + (i - off);
    }
}

// ---------------- K3 ----------------
__global__ void scatter_kernel(const int* __restrict__ numbers) {
    int a = blockIdx.x * blockDim.x + threadIdx.x;
    if (a >= N_ATOMS) return;
    int s = numbers[a];
    int pos = atomicAdd(&g_cursor[s], 1);
    g_sorted[pos] = a;
}

// ---------------- K3b: fold W1 (symmetry) + transpose + bf16 hi/lo split ----------------
__global__ void fold_w1_kernel(const float* __restrict__ W1) {
    const int total = N_SPECIES * HID * PS_SYM;
    for (int i = blockIdx.x * blockDim.x + threadIdx.x; i < total;
         i += gridDim.x * blockDim.x) {
        int k    = i % PS_SYM;
        int rest = i / PS_SYM;
        int n    = rest & (HID - 1);
        int s    = rest >> 8;
        int l    = k / NPAIR;
        int pr   = k - l * NPAIR;
        int q = g_pairq[pr], p = g_pairp[pr];
        const float* Ws = W1 + (size_t)s * PS_DIM * HID;
        float v = Ws[(size_t)(l * 1024 + q * 32 + p) * HID + n];
        if (q != p)
            v += Ws[(size_t)(l * 1024 + p * 32 + q) * HID + n];
        __nv_bfloat16 h = __float2bfloat16_rn(v);
        __nv_bfloat16 lo = __float2bfloat16_rn(v - __bfloat162float(h));
        g_w1h[i] = h;
        g_w1l[i] = lo;
    }
}

// ---------------- K3c: W2 transpose + split ----------------
__global__ void fold_w2_kernel(const float* __restrict__ W2) {
    const int total = N_SPECIES * HID * HID;
    for (int i = blockIdx.x * blockDim.x + threadIdx.x; i < total;
         i += gridDim.x * blockDim.x) {
        int k    = i & (HID - 1);
        int rest = i >> 8;
        int n    = rest & (HID - 1);
        int s    = rest >> 8;
        float v = W2[((size_t)(s * HID + k)) * HID + n];
        __nv_bfloat16 h = __float2bfloat16_rn(v);
        __nv_bfloat16 lo = __float2bfloat16_rn(v - __bfloat162float(h));
        g_w2h[i] = h;
        g_w2l[i] = lo;
    }
}

// ---------------- K4: edge featurization ----------------
__global__ void edge_kernel(const float* __restrict__ pos,
                            const float* __restrict__ cells,
                            const int* __restrict__ numbers,
                            const int* __restrict__ ei,
                            const int* __restrict__ eoff,
                            const int* __restrict__ batch) {
    int e = blockIdx.x * blockDim.x + threadIdx.x;
    if (e >= N_EDGES) return;
    int i = ei[e];
    int j = ei[N_EDGES + e];

    float pix = pos[3*i+0], piy = pos[3*i+1], piz = pos[3*i+2];
    float pjx = pos[3*j+0], pjy = pos[3*j+1], pjz = pos[3*j+2];

    int o0 = eoff[3*e+0], o1 = eoff[3*e+1], o2 = eoff[3*e+2];
    float sx = 0.f, sy = 0.f, sz = 0.f;
    if (o0 | o1 | o2) {
        int b = batch[i];
        const float* cb = cells + (size_t)b * 9;
        float f0 = (float)o0, f1 = (float)o1, f2 = (float)o2;
        sx = f0*cb[0] + f1*cb[3] + f2*cb[6];
        sy = f0*cb[1] + f1*cb[4] + f2*cb[7];
        sz = f0*cb[2] + f1*cb[5] + f2*cb[8];
    }

    float dx = pjx - pix + sx;
    float dy = pjy - piy + sy;
    float dz = pjz - piz + sz;
    float r2 = dx*dx + dy*dy + dz*dz + EPSR;
    float r  = sqrtf(r2);
    if (r >= CUTOFF) return;

    float inv = 1.0f / r;
    float a_c = r * (1.0f / CUTOFF);
    float fc  = 0.5f * (cospif(a_c) + 1.0f);
    float x = dx * inv, y = dy * inv, z = dz * inv;
    float x2 = x*x, y2 = y*y, z2 = z*z;

    float Y[16];
    Y[0]  = 0.28209479177387814f;
    Y[1]  = 0.4886025119029199f * y;
    Y[2]  = 0.4886025119029199f * z;
    Y[3]  = 0.4886025119029199f * x;
    Y[4]  = 1.0925484305920792f * x * y;
    Y[5]  = 1.0925484305920792f * y * z;
    Y[6]  = 0.31539156525252005f * (3.0f*z2 - 1.0f);
    Y[7]  = 1.0925484305920792f * x * z;
    Y[8]  = 0.5462742152960396f * (x2 - y2);
    Y[9]  = 0.5900435899266435f * y * (3.0f*x2 - y2);
    Y[10] = 2.890611442640554f  * x * y * z;
    Y[11] = 0.4570457994644658f * y * (5.0f*z2 - 1.0f);
    Y[12] = 0.3731763325901154f * z * (5.0f*z2 - 3.0f);
    Y[13] = 0.4570457994644658f * x * (5.0f*z2 - 1.0f);
    Y[14] = 1.445305721320277f  * z * (x2 - y2);
    Y[15] = 0.5900435899266435f * x * (x2 - 3.0f*y2);

    float rn[N_RADIAL];
    float scale = inv * fc;
    #pragma unroll
    for (int n = 0; n < N_RADIAL; n++)
        rn[n] = sinpif((float)(n + 1) * a_c) * scale;

    int sj = numbers[j];
    float* base = g_c + ((size_t)i * N_SPECIES + sj) * (N_RADIAL * N_SPH);

    #pragma unroll
    for (int n = 0; n < N_RADIAL; n++) {
        float rv = rn[n];
        #pragma unroll
        for (int m4 = 0; m4 < 4; m4++) {
            red4(base + n*16 + m4*4,
                 rv * Y[m4*4 + 0], rv * Y[m4*4 + 1],
                 rv * Y[m4*4 + 2], rv * Y[m4*4 + 3]);
        }
    }
}

// ---------------- K5: symmetric-packed power spectrum (conflict-free) ----------------
// c stored transposed in smem: cs[m][q], padded to 33 -> cs[m][p] is stride-1
// across lanes (p = lane-consecutive) and cs[m][q] is a broadcast.
__global__ void ps_kernel() {
    __shared__ float cs[N_SPH][Q_DIM + 1];    // 16 x 33
    __shared__ int   pq[NPAIR];
    __shared__ int   pp[NPAIR];
    int a = blockIdx.x;
    int t = threadIdx.x;      // 128
    // load 512 floats as float4 and transpose: thread t covers q=t/4, m=(t%4)*4..+3
    {
        const float4* ca = reinterpret_cast<const float4*>(g_c + (size_t)a * C_PER_ATOM);
        float4 v = ca[t];
        int q = t >> 4;               // 0..7?? no: t>>4 gives 0..7 — wrong
        // correct mapping: linear idx = t*4 -> q = (t*4)/16 = t/4, m = (t*4)%16
        q = t >> 2;                   // 0..31
        int m = (t & 3) * 4;          // 0,4,8,12
        cs[m + 0][q] = v.x;
        cs[m + 1][q] = v.y;
        cs[m + 2][q] = v.z;
        cs[m + 3][q] = v.w;
    }
    for (int i = t; i < NPAIR; i += 128) {
        pq[i] = g_pairq[i];
        pp[i] = g_pairp[i];
    }
    __syncthreads();

    const float norm[4] = {1.0f, 0.5773502691896258f, 0.4472135954999579f, 0.3779644730092272f};
    float* outp = g_ps + (size_t)a * PS_SYM;

    #pragma unroll
    for (int w = 0; w < 17; w++) {
        int idx = w * 128 + t;
        if (idx >= PS_SYM) break;
        int l  = idx / NPAIR;
        int pr = idx - l * NPAIR;
        int q = pq[pr], p = pp[pr];
        int m0 = l * l;
        int m1 = (l + 1) * (l + 1);
        float sum = 0.f;
        for (int m = m0; m < m1; m++)
            sum += cs[m][q] * cs[m][p];
        outp[idx] = sum * norm[l];
    }
}

// ---------------- K6/K7: mma.sync bf16x3-split GEMM ----------------
#define KPAD 72
#define STAGE_BF16 (128 * KPAD)
#define STAGE_BYTES (STAGE_BF16 * 2 * 2)
#define GEMM_SMEM (2 * STAGE_BYTES)

template<int WHICH>
__global__ void __launch_bounds__(256) gemm_mma_kernel() {
    constexpr int K  = (WHICH == 1) ? PS_SYM : HID;
    constexpr int NS = K / 32;

    const int item  = blockIdx.x;
    const int tile  = item >> 1;
    const int nbase = (item & 1) * 128;

    int s = -1, mloc = 0, acc = 0;
    #pragma unroll
    for (int sp = 0; sp < N_SPECIES; sp++) {
        int ts = (g_counts[sp] + 127) >> 7;
        if (s < 0 && tile < acc + ts) { s = sp; mloc = (tile - acc) << 7; }
        acc += ts;
    }
    if (s < 0) return;
    const int row0   = g_off[s] + mloc;
    const int mcount = min(128, g_counts[s] - mloc);

    extern __shared__ __nv_bfloat16 smem[];

    const int tid  = threadIdx.x;
    const int wid  = tid >> 5;
    const int lane = tid & 31;
    const int gid  = lane >> 2;
    const int tig  = lane & 3;
    const int wm   = wid & 1;
    const int wn   = wid >> 1;

    const int lrow = tid >> 1;
    const int lh   = (tid & 1) * 16;
    const bool mvalid = (lrow < mcount);
    const float* Arow = nullptr;
    if (mvalid) {
        int r = row0 + lrow;
        int src = (WHICH == 1) ? g_sorted[r] : r;
        Arow = ((WHICH == 1) ? g_ps : g_h1) + (size_t)src * K;
    }
    const __nv_bfloat16* Bhrow =
        ((WHICH == 1) ? g_w1h : g_w2h) + ((size_t)(s * HID + nbase + lrow)) * K;
    const __nv_bfloat16* Blrow =
        ((WHICH == 1) ? g_w1l : g_w2l) + ((size_t)(s * HID + nbase + lrow)) * K;

    float accum[4][4][4];
    #pragma unroll
    for (int i = 0; i < 4; i++)
        #pragma unroll
        for (int j = 0; j < 4; j++)
            #pragma unroll
            for (int e = 0; e < 4; e++) accum[i][j][e] = 0.f;

    float4 fA[4];
    uint4  vBh[2], vBl[2];

    auto load_stage = [&](int kt) {
        const int kb = kt * 32 + lh;
        if (mvalid) {
            const float4* src = reinterpret_cast<const float4*>(Arow + kb);
            fA[0] = src[0]; fA[1] = src[1]; fA[2] = src[2]; fA[3] = src[3];
        } else {
            fA[0] = fA[1] = fA[2] = fA[3] = make_float4(0.f, 0.f, 0.f, 0.f);
        }
        const uint4* bh = reinterpret_cast<const uint4*>(Bhrow + kb);
        const uint4* bl = reinterpret_cast<const uint4*>(Blrow + kb);
        vBh[0] = bh[0]; vBh[1] = bh[1];
        vBl[0] = bl[0]; vBl[1] = bl[1];
    };

    auto store_stage = [&](int buf) {
        __nv_bfloat16* As = smem + buf * 2 * STAGE_BF16;
        __nv_bfloat16* Bs = As + STAGE_BF16;
        const float* f = reinterpret_cast<const float*>(fA);
        uint32_t hiw[8], low[8];
        #pragma unroll
        for (int i = 0; i < 8; i++) {
            float v0 = f[2*i], v1 = f[2*i+1];
            __nv_bfloat16 h0 = __float2bfloat16_rn(v0);
            __nv_bfloat16 h1 = __float2bfloat16_rn(v1);
            hiw[i] = pack2(h0, h1);
            low[i] = pack2(__float2bfloat16_rn(v0 - __bfloat162float(h0)),
                           __float2bfloat16_rn(v1 - __bfloat162float(h1)));
        }
        uint4* dsthi = reinterpret_cast<uint4*>(As + lrow * KPAD + lh);
        dsthi[0] = make_uint4(hiw[0], hiw[1], hiw[2], hiw[3]);
        dsthi[1] = make_uint4(hiw[4], hiw[5], hiw[6], hiw[7]);
        uint4* dstlo = reinterpret_cast<uint4*>(As + lrow * KPAD + 32 + lh);
        dstlo[0] = make_uint4(low[0], low[1], low[2], low[3]);
        dstlo[1] = make_uint4(low[4], low[5], low[6], low[7]);
        uint4* bh = reinterpret_cast<uint4*>(Bs + lrow * KPAD + lh);
        bh[0] = vBh[0]; bh[1] = vBh[1];
        uint4* bl = reinterpret_cast<uint4*>(Bs + lrow * KPAD + 32 + lh);
        bl[0] = vBl[0]; bl[1] = vBl[1];
    };

    load_stage(0);
    store_stage(0);
    __syncthreads();

    for (int kt = 0; kt < NS; kt++) {
        const int buf = kt & 1;
        const bool has_next = (kt + 1 < NS);
        if (has_next) load_stage(kt + 1);

        const __nv_bfloat16* As = smem + buf * 2 * STAGE_BF16;
        const __nv_bfloat16* Bs = As + STAGE_BF16;
        const __nv_bfloat16* Ab = As + (wm * 64 + gid) * KPAD + 2 * tig;
        const __nv_bfloat16* Bb = Bs + (wn * 32 + gid) * KPAD + 2 * tig;

        #pragma unroll
        for (int combo = 0; combo < 3; combo++) {
            const int aoff = (combo == 1) ? 32 : 0;
            const int boff = (combo == 2) ? 32 : 0;
            #pragma unroll
            for (int kk = 0; kk < 2; kk++) {
                const int ka = aoff + kk * 16;
                const int kb = boff + kk * 16;
                uint32_t bfr[4][2];
                #pragma unroll
                for (int nt = 0; nt < 4; nt++) {
                    const __nv_bfloat16* bp = Bb + nt * 8 * KPAD + kb;
                    bfr[nt][0] = *reinterpret_cast<const uint32_t*>(bp);
                    bfr[nt][1] = *reinterpret_cast<const uint32_t*>(bp + 8);
                }
                #pragma unroll
                for (int mt = 0; mt < 4; mt++) {
                    const __nv_bfloat16* ap = Ab + mt * 16 * KPAD + ka;
                    uint32_t a0 = *reinterpret_cast<const uint32_t*>(ap);
                    uint32_t a1 = *reinterpret_cast<const uint32_t*>(ap + 8 * KPAD);
                    uint32_t a2 = *reinterpret_cast<const uint32_t*>(ap + 8);
                    uint32_t a3 = *reinterpret_cast<const uint32_t*>(ap + 8 * KPAD + 8);
                    #pragma unroll
                    for (int nt = 0; nt < 4; nt++) {
                        mma_bf16(accum[mt][nt][0], accum[mt][nt][1],
                                 accum[mt][nt][2], accum[mt][nt][3],
                                 a0, a1, a2, a3, bfr[nt][0], bfr[nt][1]);
                    }
                }
            }
        }

        if (has_next) store_stage(buf ^ 1);
        __syncthreads();
    }

    float* C = (WHICH == 1) ? g_h1 : g_h2;
    #pragma unroll
    for (int mt = 0; mt < 4; mt++) {
        int r0 = wm * 64 + mt * 16 + gid;
        int r1 = r0 + 8;
        #pragma unroll
        for (int nt = 0; nt < 4; nt++) {
            int col = nbase + wn * 32 + nt * 8 + 2 * tig;
            if (r0 < mcount) {
                float2 v; v.x = silu(accum[mt][nt][0]); v.y = silu(accum[mt][nt][1]);
                *reinterpret_cast<float2*>(&C[(size_t)(row0 + r0) * HID + col]) = v;
            }
            if (r1 < mcount) {
                float2 v; v.x = silu(accum[mt][nt][2]); v.y = silu(accum[mt][nt][3]);
                *reinterpret_cast<float2*>(&C[(size_t)(row0 + r1) * HID + col]) = v;
            }
        }
    }
}

// ---------------- K8: final projection + per-structure sum ----------------
__global__ void out_kernel(const float* __restrict__ W3,
                           const int* __restrict__ numbers,
                           const int* __restrict__ batch,
                           float* __restrict__ out) {
    int row  = blockIdx.x * 8 + (threadIdx.x >> 5);
    int lane = threadIdx.x & 31;
    if (row >= N_ATOMS) return;
    int a = g_sorted[row];
    int s = numbers[a];
    const float* h = g_h2 + (size_t)row * HID;
    const float* w = W3 + (size_t)s * HID;
    float sum = 0.f;
    #pragma unroll
    for (int k = lane; k < HID; k += 32)
        sum = fmaf(h[k], w[k], sum);
    #pragma unroll
    for (int o = 16; o > 0; o >>= 1)
        sum += __shfl_xor_sync(0xFFFFFFFFu, sum, o);
    if (lane == 0)
        atomicAdd(&out[batch[a]], sum);
}

// ---------------- launch ----------------
extern "C" void kernel_launch(void* const* d_in, const int* in_sizes, int n_in,
                              void* d_out, int out_size) {
    const float* positions    = (const float*)d_in[0];
    const float* cells        = (const float*)d_in[1];
    const int*   numbers      = (const int*)  d_in[2];
    const int*   edge_indices = (const int*)  d_in[3];
    const int*   edge_offsets = (const int*)  d_in[4];
    const int*   batch        = (const int*)  d_in[5];
    const float* Wc           = (const float*)d_in[6];
    const float* W1           = (const float*)d_in[7];
    const float* W2           = (const float*)d_in[8];
    const float* W3           = (const float*)d_in[9];
    float* out = (float*)d_out;

    cudaFuncSetAttribute(gemm_mma_kernel<1>,
                         cudaFuncAttributeMaxDynamicSharedMemorySize, GEMM_SMEM);
    cudaFuncSetAttribute(gemm_mma_kernel<2>,
                         cudaFuncAttributeMaxDynamicSharedMemorySize, GEMM_SMEM);

    zero_kernel<<<10000, 256>>>(out);
    atom_prep_kernel<<<(N_ATOMS + 255) / 256, 256>>>(numbers, batch, Wc, out);
    offsets_kernel<<<1, 256>>>();
    scatter_kernel<<<(N_ATOMS + 255) / 256, 256>>>(numbers);
    fold_w1_kernel<<<2048, 256>>>(W1);
    fold_w2_kernel<<<512, 256>>>(W2);
    edge_kernel<<<N_EDGES / 256, 256>>>(positions, cells, numbers,
                                        edge_indices, edge_offsets, batch);
    ps_kernel<<<N_ATOMS, 128>>>();

    gemm_mma_kernel<1><<<MAX_TILES * 2, 256, GEMM_SMEM>>>();
    gemm_mma_kernel<2><<<MAX_TILES * 2, 256, GEMM_SMEM>>>();
    out_kernel<<<(N_ATOMS + 7) / 8, 256>>>(W3, numbers, batch, out);
}

// round 6
// speedup vs baseline: 3.6975x; 1.0532x over previous
#include <cuda_runtime.h>
#include <cuda_bf16.h>
#include <math.h>
#include <stdint.h>

// ---------------- problem constants ----------------
#define N_ATOMS   20000
#define N_EDGES   640000
#define N_STRUCT  100
#define N_SPECIES 4
#define N_RADIAL  8
#define N_SPH     16
#define Q_DIM     32
#define C_PER_ATOM 512
#define PS_DIM    4096
#define NPAIR     528
#define PS_SYM    2112              // 33 * 64 = 66 * 32
#define HID       256
#define CUTOFF    5.0f
#define EPSR      1e-12f
#define MAX_TILES 160

// ---------------- scratch ----------------
__device__ float g_c  [(size_t)N_ATOMS * C_PER_ATOM];
__device__ float g_ps [(size_t)N_ATOMS * PS_SYM];
__device__ float g_h1 [(size_t)N_ATOMS * HID];
__device__ float g_h2 [(size_t)N_ATOMS * HID];
__device__ __nv_bfloat16 g_w1h[(size_t)N_SPECIES * HID * PS_SYM];
__device__ __nv_bfloat16 g_w1l[(size_t)N_SPECIES * HID * PS_SYM];
__device__ __nv_bfloat16 g_w2h[(size_t)N_SPECIES * HID * HID];
__device__ __nv_bfloat16 g_w2l[(size_t)N_SPECIES * HID * HID];
__device__ int   g_pairq[NPAIR];
__device__ int   g_pairp[NPAIR];
__device__ int   g_counts[N_SPECIES];
__device__ int   g_off[N_SPECIES];
__device__ int   g_cursor[N_SPECIES];
__device__ int   g_sorted[N_ATOMS];

// ---------------- helpers ----------------
__device__ __forceinline__ float silu(float x) { return x / (1.0f + expf(-x)); }

__device__ __forceinline__ void red4(float* p, float a, float b, float c, float d) {
    asm volatile("red.global.add.v4.f32 [%0], {%1,%2,%3,%4};"
                 :: "l"(p), "f"(a), "f"(b), "f"(c), "f"(d) : "memory");
}

__device__ __forceinline__ uint32_t pack2(__nv_bfloat16 a, __nv_bfloat16 b) {
    return (uint32_t)__bfloat16_as_ushort(a) | ((uint32_t)__bfloat16_as_ushort(b) << 16);
}

__device__ __forceinline__ void mma_bf16(float& c0, float& c1, float& c2, float& c3,
                                         uint32_t a0, uint32_t a1, uint32_t a2, uint32_t a3,
                                         uint32_t b0, uint32_t b1) {
    asm volatile("mma.sync.aligned.m16n8k16.row.col.f32.bf16.bf16.f32 "
                 "{%0,%1,%2,%3}, {%4,%5,%6,%7}, {%8,%9}, {%0,%1,%2,%3};"
                 : "+f"(c0), "+f"(c1), "+f"(c2), "+f"(c3)
                 : "r"(a0), "r"(a1), "r"(a2), "r"(a3), "r"(b0), "r"(b1));
}

__device__ __forceinline__ void ldmatrix_x4(uint32_t& r0, uint32_t& r1,
                                            uint32_t& r2, uint32_t& r3, uint32_t addr) {
    asm volatile("ldmatrix.sync.aligned.m8n8.x4.shared.b16 {%0,%1,%2,%3}, [%4];"
                 : "=r"(r0), "=r"(r1), "=r"(r2), "=r"(r3) : "r"(addr));
}

// ---------------- K0: zero ----------------
__global__ void zero_kernel(float* __restrict__ out) {
    size_t idx = (size_t)blockIdx.x * blockDim.x + threadIdx.x;
    float4* c4 = reinterpret_cast<float4*>(g_c);
    c4[idx] = make_float4(0.f, 0.f, 0.f, 0.f);
    if (idx < N_STRUCT) out[idx] = 0.f;
    if (idx < N_SPECIES) g_counts[idx] = 0;
}

// ---------------- K1 ----------------
__global__ void atom_prep_kernel(const int* __restrict__ numbers,
                                 const int* __restrict__ batch,
                                 const float* __restrict__ Wc,
                                 float* __restrict__ out) {
    int a = blockIdx.x * blockDim.x + threadIdx.x;
    if (a >= N_ATOMS) return;
    int s = numbers[a];
    atomicAdd(&g_counts[s], 1);
    atomicAdd(&out[batch[a]], Wc[s]);
}

// ---------------- K2 ----------------
__global__ void offsets_kernel() {
    int t = threadIdx.x;
    if (t == 0) {
        int acc = 0;
        for (int s = 0; s < N_SPECIES; s++) {
            g_off[s] = acc;
            g_cursor[s] = acc;
            acc += g_counts[s];
        }
    }
    for (int i = t; i < NPAIR; i += blockDim.x) {
        int q = 0, off = 0;
        while (off + (Q_DIM - q) <= i) { off += Q_DIM - q; q++; }
        g_pairq[i] = q;
        g_pairp[i] = q + (i - off);
    }
}

// ---------------- K3 ----------------
__global__ void scatter_kernel(const int* __restrict__ numbers) {
    int a = blockIdx.x * blockDim.x + threadIdx.x;
    if (a >= N_ATOMS) return;
    int s = numbers[a];
    int pos = atomicAdd(&g_cursor[s], 1);
    g_sorted[pos] = a;
}

// ---------------- K3b: fold W1 + transpose + split (coalesced both sides) ----------------
// grid (66, 8, 4), block (32, 32): read (k=bx*32+ty, n=by*32+tx) coalesced over n,
// transpose via smem tile, write (n'=by*32+ty, k'=bx*32+tx) coalesced over k.
__global__ void fold_w1_kernel(const float* __restrict__ W1) {
    __shared__ float tile[32][33];
    int tx = threadIdx.x, ty = threadIdx.y;
    int k = blockIdx.x * 32 + ty;
    int n = blockIdx.y * 32 + tx;
    int l  = k / NPAIR;
    int pr = k - l * NPAIR;
    int q = g_pairq[pr], p = g_pairp[pr];
    const float* Ws = W1 + (size_t)blockIdx.z * PS_DIM * HID;
    float v = Ws[(size_t)(l * 1024 + q * 32 + p) * HID + n];
    if (q != p)
        v += Ws[(size_t)(l * 1024 + p * 32 + q) * HID + n];
    tile[ty][tx] = v;
    __syncthreads();
    int nn = blockIdx.y * 32 + ty;
    int kk = blockIdx.x * 32 + tx;
    float w = tile[tx][ty];
    __nv_bfloat16 h = __float2bfloat16_rn(w);
    size_t oi = ((size_t)(blockIdx.z * HID + nn)) * PS_SYM + kk;
    g_w1h[oi] = h;
    g_w1l[oi] = __float2bfloat16_rn(w - __bfloat162float(h));
}

// ---------------- K3c: W2 transpose + split ----------------
__global__ void fold_w2_kernel(const float* __restrict__ W2) {
    __shared__ float tile[32][33];
    int tx = threadIdx.x, ty = threadIdx.y;
    int k = blockIdx.x * 32 + ty;
    int n = blockIdx.y * 32 + tx;
    tile[ty][tx] = W2[((size_t)(blockIdx.z * HID + k)) * HID + n];
    __syncthreads();
    int nn = blockIdx.y * 32 + ty;
    int kk = blockIdx.x * 32 + tx;
    float w = tile[tx][ty];
    __nv_bfloat16 h = __float2bfloat16_rn(w);
    size_t oi = ((size_t)(blockIdx.z * HID + nn)) * HID + kk;
    g_w2h[oi] = h;
    g_w2l[oi] = __float2bfloat16_rn(w - __bfloat162float(h));
}

// ---------------- K4: edge featurization ----------------
__global__ void edge_kernel(const float* __restrict__ pos,
                            const float* __restrict__ cells,
                            const int* __restrict__ numbers,
                            const int* __restrict__ ei,
                            const int* __restrict__ eoff,
                            const int* __restrict__ batch) {
    int e = blockIdx.x * blockDim.x + threadIdx.x;
    if (e >= N_EDGES) return;
    int i = ei[e];
    int j = ei[N_EDGES + e];

    float pix = pos[3*i+0], piy = pos[3*i+1], piz = pos[3*i+2];
    float pjx = pos[3*j+0], pjy = pos[3*j+1], pjz = pos[3*j+2];

    int o0 = eoff[3*e+0], o1 = eoff[3*e+1], o2 = eoff[3*e+2];
    float sx = 0.f, sy = 0.f, sz = 0.f;
    if (o0 | o1 | o2) {
        int b = batch[i];
        const float* cb = cells + (size_t)b * 9;
        float f0 = (float)o0, f1 = (float)o1, f2 = (float)o2;
        sx = f0*cb[0] + f1*cb[3] + f2*cb[6];
        sy = f0*cb[1] + f1*cb[4] + f2*cb[7];
        sz = f0*cb[2] + f1*cb[5] + f2*cb[8];
    }

    float dx = pjx - pix + sx;
    float dy = pjy - piy + sy;
    float dz = pjz - piz + sz;
    float r2 = dx*dx + dy*dy + dz*dz + EPSR;
    float r  = sqrtf(r2);
    if (r >= CUTOFF) return;

    float inv = 1.0f / r;
    float a_c = r * (1.0f / CUTOFF);
    float fc  = 0.5f * (cospif(a_c) + 1.0f);
    float x = dx * inv, y = dy * inv, z = dz * inv;
    float x2 = x*x, y2 = y*y, z2 = z*z;

    float Y[16];
    Y[0]  = 0.28209479177387814f;
    Y[1]  = 0.4886025119029199f * y;
    Y[2]  = 0.4886025119029199f * z;
    Y[3]  = 0.4886025119029199f * x;
    Y[4]  = 1.0925484305920792f * x * y;
    Y[5]  = 1.0925484305920792f * y * z;
    Y[6]  = 0.31539156525252005f * (3.0f*z2 - 1.0f);
    Y[7]  = 1.0925484305920792f * x * z;
    Y[8]  = 0.5462742152960396f * (x2 - y2);
    Y[9]  = 0.5900435899266435f * y * (3.0f*x2 - y2);
    Y[10] = 2.890611442640554f  * x * y * z;
    Y[11] = 0.4570457994644658f * y * (5.0f*z2 - 1.0f);
    Y[12] = 0.3731763325901154f * z * (5.0f*z2 - 3.0f);
    Y[13] = 0.4570457994644658f * x * (5.0f*z2 - 1.0f);
    Y[14] = 1.445305721320277f  * z * (x2 - y2);
    Y[15] = 0.5900435899266435f * x * (x2 - 3.0f*y2);

    float rn[N_RADIAL];
    float scale = inv * fc;
    #pragma unroll
    for (int n = 0; n < N_RADIAL; n++)
        rn[n] = sinpif((float)(n + 1) * a_c) * scale;

    int sj = numbers[j];
    float* base = g_c + ((size_t)i * N_SPECIES + sj) * (N_RADIAL * N_SPH);

    #pragma unroll
    for (int n = 0; n < N_RADIAL; n++) {
        float rv = rn[n];
        #pragma unroll
        for (int m4 = 0; m4 < 4; m4++) {
            red4(base + n*16 + m4*4,
                 rv * Y[m4*4 + 0], rv * Y[m4*4 + 1],
                 rv * Y[m4*4 + 2], rv * Y[m4*4 + 3]);
        }
    }
}

// ---------------- K5: power spectrum (conflict-free m-major smem) ----------------
__global__ void ps_kernel() {
    __shared__ float cs[N_SPH][Q_DIM + 1];
    __shared__ int   pq[NPAIR];
    __shared__ int   pp[NPAIR];
    int a = blockIdx.x;
    int t = threadIdx.x;      // 128
    {
        const float4* ca = reinterpret_cast<const float4*>(g_c + (size_t)a * C_PER_ATOM);
        float4 v = ca[t];
        int q = t >> 2;               // 0..31
        int m = (t & 3) * 4;          // 0,4,8,12
        cs[m + 0][q] = v.x;
        cs[m + 1][q] = v.y;
        cs[m + 2][q] = v.z;
        cs[m + 3][q] = v.w;
    }
    for (int i = t; i < NPAIR; i += 128) {
        pq[i] = g_pairq[i];
        pp[i] = g_pairp[i];
    }
    __syncthreads();

    const float norm[4] = {1.0f, 0.5773502691896258f, 0.4472135954999579f, 0.3779644730092272f};
    float* outp = g_ps + (size_t)a * PS_SYM;

    #pragma unroll
    for (int w = 0; w < 17; w++) {
        int idx = w * 128 + t;
        if (idx >= PS_SYM) break;
        int l  = idx / NPAIR;
        int pr = idx - l * NPAIR;
        int q = pq[pr], p = pp[pr];
        int m0 = l * l;
        int m1 = (l + 1) * (l + 1);
        float sum = 0.f;
        for (int m = m0; m < m1; m++)
            sum += cs[m][q] * cs[m][p];
        outp[idx] = sum * norm[l];
    }
}

// ---------------- K6/K7: mma.sync bf16x3-split GEMM with ldmatrix ----------------
#define KPAD 72
#define STAGE_BF16 (128 * KPAD)
#define STAGE_BYTES (STAGE_BF16 * 2 * 2)
#define GEMM_SMEM (2 * STAGE_BYTES)

template<int WHICH>
__global__ void __launch_bounds__(256) gemm_mma_kernel() {
    constexpr int K  = (WHICH == 1) ? PS_SYM : HID;
    constexpr int NS = K / 32;

    const int item  = blockIdx.x;
    const int tile  = item >> 1;
    const int nbase = (item & 1) * 128;

    int s = -1, mloc = 0, acc = 0;
    #pragma unroll
    for (int sp = 0; sp < N_SPECIES; sp++) {
        int ts = (g_counts[sp] + 127) >> 7;
        if (s < 0 && tile < acc + ts) { s = sp; mloc = (tile - acc) << 7; }
        acc += ts;
    }
    if (s < 0) return;
    const int row0   = g_off[s] + mloc;
    const int mcount = min(128, g_counts[s] - mloc);

    extern __shared__ __nv_bfloat16 smem[];

    const int tid  = threadIdx.x;
    const int wid  = tid >> 5;
    const int lane = tid & 31;
    const int gid  = lane >> 2;
    const int tig  = lane & 3;
    const int wm   = wid & 1;
    const int wn   = wid >> 1;

    const int lrow = tid >> 1;
    const int lh   = (tid & 1) * 16;
    const bool mvalid = (lrow < mcount);
    const float* Arow = nullptr;
    if (mvalid) {
        int r = row0 + lrow;
        int src = (WHICH == 1) ? g_sorted[r] : r;
        Arow = ((WHICH == 1) ? g_ps : g_h1) + (size_t)src * K;
    }
    const __nv_bfloat16* Bhrow =
        ((WHICH == 1) ? g_w1h : g_w2h) + ((size_t)(s * HID + nbase + lrow)) * K;
    const __nv_bfloat16* Blrow =
        ((WHICH == 1) ? g_w1l : g_w2l) + ((size_t)(s * HID + nbase + lrow)) * K;

    float accum[4][4][4];
    #pragma unroll
    for (int i = 0; i < 4; i++)
        #pragma unroll
        for (int j = 0; j < 4; j++)
            #pragma unroll
            for (int e = 0; e < 4; e++) accum[i][j][e] = 0.f;

    float4 fA[4];
    uint4  vBh[2], vBl[2];

    auto load_stage = [&](int kt) {
        const int kb = kt * 32 + lh;
        if (mvalid) {
            const float4* src = reinterpret_cast<const float4*>(Arow + kb);
            fA[0] = src[0]; fA[1] = src[1]; fA[2] = src[2]; fA[3] = src[3];
        } else {
            fA[0] = fA[1] = fA[2] = fA[3] = make_float4(0.f, 0.f, 0.f, 0.f);
        }
        const uint4* bh = reinterpret_cast<const uint4*>(Bhrow + kb);
        const uint4* bl = reinterpret_cast<const uint4*>(Blrow + kb);
        vBh[0] = bh[0]; vBh[1] = bh[1];
        vBl[0] = bl[0]; vBl[1] = bl[1];
    };

    auto store_stage = [&](int buf) {
        __nv_bfloat16* As = smem + buf * 2 * STAGE_BF16;
        __nv_bfloat16* Bs = As + STAGE_BF16;
        const float* f = reinterpret_cast<const float*>(fA);
        uint32_t hiw[8], low[8];
        #pragma unroll
        for (int i = 0; i < 8; i++) {
            float v0 = f[2*i], v1 = f[2*i+1];
            __nv_bfloat16 h0 = __float2bfloat16_rn(v0);
            __nv_bfloat16 h1 = __float2bfloat16_rn(v1);
            hiw[i] = pack2(h0, h1);
            low[i] = pack2(__float2bfloat16_rn(v0 - __bfloat162float(h0)),
                           __float2bfloat16_rn(v1 - __bfloat162float(h1)));
        }
        uint4* dsthi = reinterpret_cast<uint4*>(As + lrow * KPAD + lh);
        dsthi[0] = make_uint4(hiw[0], hiw[1], hiw[2], hiw[3]);
        dsthi[1] = make_uint4(hiw[4], hiw[5], hiw[6], hiw[7]);
        uint4* dstlo = reinterpret_cast<uint4*>(As + lrow * KPAD + 32 + lh);
        dstlo[0] = make_uint4(low[0], low[1], low[2], low[3]);
        dstlo[1] = make_uint4(low[4], low[5], low[6], low[7]);
        uint4* bh = reinterpret_cast<uint4*>(Bs + lrow * KPAD + lh);
        bh[0] = vBh[0]; bh[1] = vBh[1];
        uint4* bl = reinterpret_cast<uint4*>(Bs + lrow * KPAD + 32 + lh);
        bl[0] = vBl[0]; bl[1] = vBl[1];
    };

    // ldmatrix lane-address bases (bytes, shared-space)
    // A x4: lanes 0-7 m0-7@k, 8-15 m8-15@k, 16-23 m0-7@k+8, 24-31 m8-15@k+8
    // B x4: lanes 0-7 n0-7@k, 8-15 n0-7@k+8, 16-23 n8-15@k, 24-31 n8-15@k+8
    const uint32_t smem_sh = (uint32_t)__cvta_generic_to_shared(smem);
    uint32_t aOff[4], bOff[2];
    #pragma unroll
    for (int mt = 0; mt < 4; mt++)
        aOff[mt] = (uint32_t)(((wm * 64 + mt * 16 + (lane & 15)) * KPAD
                               + (lane >> 4) * 8) * 2);
    #pragma unroll
    for (int ng = 0; ng < 2; ng++)
        bOff[ng] = (uint32_t)(((wn * 32 + ng * 16 + ((lane >> 4) << 3) + (lane & 7)) * KPAD
                               + ((lane >> 3) & 1) * 8) * 2);

    load_stage(0);
    store_stage(0);
    __syncthreads();

    for (int kt = 0; kt < NS; kt++) {
        const int buf = kt & 1;
        const bool has_next = (kt + 1 < NS);
        if (has_next) load_stage(kt + 1);

        const uint32_t sA = smem_sh + buf * 2 * STAGE_BF16 * 2;
        const uint32_t sB = sA + STAGE_BF16 * 2;

        #pragma unroll
        for (int combo = 0; combo < 3; combo++) {
            const int aoff = (combo == 1) ? 32 : 0;
            const int boff = (combo == 2) ? 32 : 0;
            #pragma unroll
            for (int kk = 0; kk < 2; kk++) {
                const uint32_t ka2 = (aoff + kk * 16) * 2;
                const uint32_t kb2 = (boff + kk * 16) * 2;
                uint32_t b0[4], b1[4];
                ldmatrix_x4(b0[0], b0[1], b0[2], b0[3], sB + bOff[0] + kb2);
                ldmatrix_x4(b1[0], b1[1], b1[2], b1[3], sB + bOff[1] + kb2);
                #pragma unroll
                for (int mt = 0; mt < 4; mt++) {
                    uint32_t a0, a1, a2, a3;
                    ldmatrix_x4(a0, a1, a2, a3, sA + aOff[mt] + ka2);
                    mma_bf16(accum[mt][0][0], accum[mt][0][1], accum[mt][0][2], accum[mt][0][3],
                             a0, a1, a2, a3, b0[0], b0[1]);
                    mma_bf16(accum[mt][1][0], accum[mt][1][1], accum[mt][1][2], accum[mt][1][3],
                             a0, a1, a2, a3, b0[2], b0[3]);
                    mma_bf16(accum[mt][2][0], accum[mt][2][1], accum[mt][2][2], accum[mt][2][3],
                             a0, a1, a2, a3, b1[0], b1[1]);
                    mma_bf16(accum[mt][3][0], accum[mt][3][1], accum[mt][3][2], accum[mt][3][3],
                             a0, a1, a2, a3, b1[2], b1[3]);
                }
            }
        }

        if (has_next) store_stage(buf ^ 1);
        __syncthreads();
    }

    float* C = (WHICH == 1) ? g_h1 : g_h2;
    #pragma unroll
    for (int mt = 0; mt < 4; mt++) {
        int r0 = wm * 64 + mt * 16 + gid;
        int r1 = r0 + 8;
        #pragma unroll
        for (int nt = 0; nt < 4; nt++) {
            int col = nbase + wn * 32 + nt * 8 + 2 * tig;
            if (r0 < mcount) {
                float2 v; v.x = silu(accum[mt][nt][0]); v.y = silu(accum[mt][nt][1]);
                *reinterpret_cast<float2*>(&C[(size_t)(row0 + r0) * HID + col]) = v;
            }
            if (r1 < mcount) {
                float2 v; v.x = silu(accum[mt][nt][2]); v.y = silu(accum[mt][nt][3]);
                *reinterpret_cast<float2*>(&C[(size_t)(row0 + r1) * HID + col]) = v;
            }
        }
    }
}

// ---------------- K8: final projection + per-structure sum ----------------
__global__ void out_kernel(const float* __restrict__ W3,
                           const int* __restrict__ numbers,
                           const int* __restrict__ batch,
                           float* __restrict__ out) {
    int row  = blockIdx.x * 8 + (threadIdx.x >> 5);
    int lane = threadIdx.x & 31;
    if (row >= N_ATOMS) return;
    int a = g_sorted[row];
    int s = numbers[a];
    const float* h = g_h2 + (size_t)row * HID;
    const float* w = W3 + (size_t)s * HID;
    float sum = 0.f;
    #pragma unroll
    for (int k = lane; k < HID; k += 32)
        sum = fmaf(h[k], w[k], sum);
    #pragma unroll
    for (int o = 16; o > 0; o >>= 1)
        sum += __shfl_xor_sync(0xFFFFFFFFu, sum, o);
    if (lane == 0)
        atomicAdd(&out[batch[a]], sum);
}

// ---------------- launch ----------------
extern "C" void kernel_launch(void* const* d_in, const int* in_sizes, int n_in,
                              void* d_out, int out_size) {
    const float* positions    = (const float*)d_in[0];
    const float* cells        = (const float*)d_in[1];
    const int*   numbers      = (const int*)  d_in[2];
    const int*   edge_indices = (const int*)  d_in[3];
    const int*   edge_offsets = (const int*)  d_in[4];
    const int*   batch        = (const int*)  d_in[5];
    const float* Wc           = (const float*)d_in[6];
    const float* W1           = (const float*)d_in[7];
    const float* W2           = (const float*)d_in[8];
    const float* W3           = (const float*)d_in[9];
    float* out = (float*)d_out;

    cudaFuncSetAttribute(gemm_mma_kernel<1>,
                         cudaFuncAttributeMaxDynamicSharedMemorySize, GEMM_SMEM);
    cudaFuncSetAttribute(gemm_mma_kernel<2>,
                         cudaFuncAttributeMaxDynamicSharedMemorySize, GEMM_SMEM);

    zero_kernel<<<10000, 256>>>(out);
    atom_prep_kernel<<<(N_ATOMS + 255) / 256, 256>>>(numbers, batch, Wc, out);
    offsets_kernel<<<1, 256>>>();
    scatter_kernel<<<(N_ATOMS + 255) / 256, 256>>>(numbers);
    fold_w1_kernel<<<dim3(66, 8, 4), dim3(32, 32)>>>(W1);
    fold_w2_kernel<<<dim3(8, 8, 4), dim3(32, 32)>>>(W2);
    edge_kernel<<<N_EDGES / 256, 256>>>(positions, cells, numbers,
                                        edge_indices, edge_offsets, batch);
    ps_kernel<<<N_ATOMS, 128>>>();

    gemm_mma_kernel<1><<<MAX_TILES * 2, 256, GEMM_SMEM>>>();
    gemm_mma_kernel<2><<<MAX_TILES * 2, 256, GEMM_SMEM>>>();
    out_kernel<<<(N_ATOMS + 7) / 8, 256>>>(W3, numbers, batch, out);
}